// round 13
// baseline (speedup 1.0000x reference)
#include <cuda_runtime.h>
#include <cuda_bf16.h>
#include <cuda_fp16.h>
#include <math.h>
#include <stdint.h>

#define N_NODES 50000
#define N_EDGES 1200000
#define N_OD    10000
#define D_NODE  16
#define D_EDGE  8
#define HID     64
#define N_LAYERS 3
#define TILE_E  128
#define N_TILES (N_EDGES / TILE_E)   // 9375 exactly
#define EA_TILE_BYTES 16384          // fp16 e tile: 128 rows x 128B

#if defined(__CUDA_ARCH__) && (defined(__CUDA_ARCH_FEAT_SM103_ALL) || defined(__CUDA_ARCH_FEAT_SM100_ALL))
#define USE_TC 1
#else
#define USE_TC 0
#endif

// persistent scratch
__device__ float g_h[N_NODES * HID];
__device__ float g_agg[N_NODES * HID];
__device__ float g_z[N_NODES * HID];     // z = h @ Wm_top (per layer)
__device__ float g_gsum[HID];
// layer-invariant edge features, fp16, pre-swizzled A-tile layout
__device__ __align__(1024) char g_eA[(size_t)N_TILES * EA_TILE_BYTES];

// ---------------------------------------------------------------------------
// helpers
// ---------------------------------------------------------------------------
__device__ __forceinline__ void red_add_v4(float* p, float a, float b, float c, float d) {
    asm volatile("red.global.add.v4.f32 [%0], {%1, %2, %3, %4};"
                 :: "l"(p), "f"(a), "f"(b), "f"(c), "f"(d) : "memory");
}

#if USE_TC
__device__ __forceinline__ uint32_t elect_one_pred() {
    uint32_t pred;
    asm volatile(
        "{\n\t.reg .pred p;\n\t"
        "elect.sync _|p, 0xFFFFFFFF;\n\t"
        "selp.b32 %0, 1, 0, p;\n\t}"
        : "=r"(pred));
    return pred;
}
#endif

__device__ __forceinline__ uint32_t smem_u32(const void* p) {
    uint32_t a;
    asm("{ .reg .u64 t; cvta.to.shared.u64 t, %1; cvt.u32.u64 %0, t; }"
        : "=r"(a) : "l"(p));
    return a;
}
#define SW128(o) ((o) ^ (((o) >> 3) & 0x70))

static constexpr uint64_t SMEM_DESC_BASE_SW128 =
    (uint64_t(2)  << 61) | (uint64_t(1) << 46) | (uint64_t(64) << 32) | (uint64_t(1) << 16);
#define MAKE_SMEM_DESC(base_addr) \
    (SMEM_DESC_BASE_SW128 | ((uint64_t)((base_addr) >> 4) & 0x3FFF))

#if USE_TC
#define TCGEN05_ALLOC(smem_result_addr, nCols) \
    asm volatile("tcgen05.alloc.cta_group::1.sync.aligned.shared::cta.b32 [%0], %1;" \
        :: "r"((uint32_t)(smem_result_addr)), "r"((uint32_t)(nCols)) : "memory")
#define TCGEN05_DEALLOC(tmem_addr, nCols) \
    asm volatile("tcgen05.dealloc.cta_group::1.sync.aligned.b32 %0, %1;" \
        :: "r"(tmem_addr), "r"((uint32_t)(nCols)))
#define TCGEN05_RELINQ() \
    asm volatile("tcgen05.relinquish_alloc_permit.cta_group::1.sync.aligned;")
#define TCGEN05_COMMIT(mbar_smem_addr) \
    asm volatile("tcgen05.commit.cta_group::1.mbarrier::arrive::one.shared::cluster.b64 [%0];" \
        :: "r"((uint32_t)(mbar_smem_addr)) : "memory")
#define TCGEN05_WAIT_LD() \
    asm volatile("tcgen05.wait::ld.sync.aligned;" ::: "memory")
#define TCGEN05_FENCE_BEFORE() \
    asm volatile("tcgen05.fence::before_thread_sync;" ::: "memory")
#define TCGEN05_FENCE_AFTER() \
    asm volatile("tcgen05.fence::after_thread_sync;" ::: "memory")
#define FENCE_PROXY_ASYNC() \
    asm volatile("fence.proxy.async.shared::cta;" ::: "memory")
#define MBARRIER_INIT(mbar, count) \
    asm volatile("mbarrier.init.shared.b64 [%0], %1;" \
        :: "r"((uint32_t)(mbar)), "r"((uint32_t)(count)) : "memory")
#define MBARRIER_EXPECT_TX(mbar, bytes) \
    asm volatile("mbarrier.arrive.expect_tx.shared.b64 _, [%0], %1;" \
        :: "r"((uint32_t)(mbar)), "r"((uint32_t)(bytes)) : "memory")
#define CP_BULK_G2S(dst, src, bytes, mbar) \
    asm volatile("cp.async.bulk.shared::cluster.global.mbarrier::complete_tx::bytes [%0], [%1], %2, [%3];" \
        :: "r"((uint32_t)(dst)), "l"(src), "r"((uint32_t)(bytes)), "r"((uint32_t)(mbar)) : "memory")
#define MBARRIER_WAIT_PARITY(mbar_smem_addr, phase_parity) do { \
    uint32_t _mbar = (uint32_t)(mbar_smem_addr); \
    uint32_t _parity = (uint32_t)(phase_parity); \
    uint32_t _done; \
    asm volatile( \
        "{\n\t.reg .pred p;\n\t" \
        "mbarrier.try_wait.parity.acquire.cta.shared::cta.b64 p, [%1], %2;\n\t" \
        "selp.b32 %0, 1, 0, p;\n\t}" \
        : "=r"(_done) : "r"(_mbar), "r"(_parity) : "memory"); \
    if (!_done) { \
        asm volatile( \
            "{\n\t.reg .pred P1;\n\t" \
            "WAIT_LOOP_%=:\n\t" \
            "mbarrier.try_wait.parity.acquire.cta.shared::cta.b64 P1, [%0], %1, 0x989680;\n\t" \
            "@P1 bra.uni WAIT_DONE_%=;\n\t" \
            "bra.uni WAIT_LOOP_%=;\n\t" \
            "WAIT_DONE_%=:\n\t}" \
            :: "r"(_mbar), "r"(_parity) : "memory"); \
    } \
} while(0)

#define TCGEN05_LD_32X32B_X32(r, tmem_addr) \
    asm volatile( \
        "tcgen05.ld.sync.aligned.32x32b.x32.b32 " \
        "{%0, %1, %2, %3, %4, %5, %6, %7, " \
        " %8, %9, %10, %11, %12, %13, %14, %15, " \
        " %16, %17, %18, %19, %20, %21, %22, %23, " \
        " %24, %25, %26, %27, %28, %29, %30, %31}, [%32];" \
        : "=r"((r)[0]),  "=r"((r)[1]),  "=r"((r)[2]),  "=r"((r)[3]), \
          "=r"((r)[4]),  "=r"((r)[5]),  "=r"((r)[6]),  "=r"((r)[7]), \
          "=r"((r)[8]),  "=r"((r)[9]),  "=r"((r)[10]), "=r"((r)[11]), \
          "=r"((r)[12]), "=r"((r)[13]), "=r"((r)[14]), "=r"((r)[15]), \
          "=r"((r)[16]), "=r"((r)[17]), "=r"((r)[18]), "=r"((r)[19]), \
          "=r"((r)[20]), "=r"((r)[21]), "=r"((r)[22]), "=r"((r)[23]), \
          "=r"((r)[24]), "=r"((r)[25]), "=r"((r)[26]), "=r"((r)[27]), \
          "=r"((r)[28]), "=r"((r)[29]), "=r"((r)[30]), "=r"((r)[31]) \
        : "r"(tmem_addr))

__device__ __forceinline__ void mma_f16_ss(uint32_t d_tmem, uint64_t a_desc,
                                           uint64_t b_desc, uint32_t idesc,
                                           uint32_t acc) {
    asm volatile(
        "{\n\t.reg .pred p;\n\t"
        "setp.ne.u32 p, %5, 0;\n\t"
        "tcgen05.mma.cta_group::1.kind::f16 [%0], %1, %2, %3, {%4, %4, %4, %4}, p;\n\t"
        "}"
        :: "r"(d_tmem), "l"(a_desc), "l"(b_desc), "r"(idesc), "r"(0u), "r"(acc)
        : "memory");
}
#endif // USE_TC

// idesc: D=F32, A=FP16, B=FP16, N=64, M=128
#define MMA_IDESC 0x08100010u

// tensor-path smem byte offsets (from 1024-aligned base) — triple fp16 A bufs
#define OFF_A0   0        // 16KB
#define OFF_A1   16384
#define OFF_A2   32768
#define OFF_W_HI 49152    // 8KB
#define OFF_W_LO 57344    // 8KB
#define OFF_SM   65536    // 128 x 68 floats = 34816
#define OFF_BM   100352   // 64 floats
#define OFF_SRC  100608   // 3 x 128 ints = 1536
#define OFF_DST  102144   // 1536
#define OFF_TPTR 103680
#define OFF_CMB0 103688
#define OFF_CMB1 103696
#define OFF_CMB2 103704
#define OFF_MMB0 103712
#define OFF_MMB1 103720
// fallback-path smem offsets
#define FOFF_E    0       // 128 x 68 floats = 34816B
#define FOFF_WM   34816   // 64 x 64 floats = 16384B
#define FOFF_SWE  51200
#define FOFF_BE   53248
#define FOFF_BM   53504
#define FOFF_SRC  53760
#define FOFF_DST  54272
#define SMEM_EDGE_BYTES 104960

// ---------------------------------------------------------------------------
// One-time: e = relu(EF @ We + be), fp16, pre-swizzled A-tile layout.
// ---------------------------------------------------------------------------
__global__ void __launch_bounds__(256)
edge_e_kernel(const float* __restrict__ ef,
              const float* __restrict__ We,
              const float* __restrict__ be) {
    __shared__ float sWe[D_EDGE * HID];
    __shared__ float sbe[HID];
    int t = threadIdx.x;
    for (int i = t; i < D_EDGE * HID; i += 256) sWe[i] = We[i];
    if (t < 64) sbe[t] = be[t];
    __syncthreads();

    int tile = blockIdx.x;
    int eb = tile * TILE_E;
    int r = t >> 1, hf = t & 1;
    char* a_tile = g_eA + (size_t)tile * EA_TILE_BYTES;

    const float4* e4 = (const float4*)(ef + (size_t)(eb + r) * D_EDGE);
    float4 e0 = __ldg(e4), e1 = __ldg(e4 + 1);
    float xf[8] = {e0.x, e0.y, e0.z, e0.w, e1.x, e1.y, e1.z, e1.w};
#pragma unroll
    for (int g = 0; g < 8; g++) {
        int c0 = hf * 32 + g * 4;
        float4 acc = *(const float4*)(sbe + c0);
#pragma unroll
        for (int k = 0; k < 8; k++) {
            float4 wv = *(const float4*)(sWe + k * HID + c0);
            acc.x += xf[k] * wv.x; acc.y += xf[k] * wv.y;
            acc.z += xf[k] * wv.z; acc.w += xf[k] * wv.w;
        }
        acc.x = fmaxf(acc.x, 0.f); acc.y = fmaxf(acc.y, 0.f);
        acc.z = fmaxf(acc.z, 0.f); acc.w = fmaxf(acc.w, 0.f);
        __half2 p0 = __floats2half2_rn(acc.x, acc.y);
        __half2 p1 = __floats2half2_rn(acc.z, acc.w);
        uint2 v;
        v.x = *reinterpret_cast<uint32_t*>(&p0);
        v.y = *reinterpret_cast<uint32_t*>(&p1);
        uint32_t sw = SW128((uint32_t)(r * 128 + c0 * 2));
        *(uint2*)(a_tile + sw) = v;
    }
}

// ---------------------------------------------------------------------------
// Edge message kernel (persistent, depth-2 pipeline: 3 A buffers, copy issued
// 2 tiles ahead; 2 TMEM accumulators, MMA issued 1 tile ahead):
//   c = e @ Wm_bot (tcgen05 fp16); m = relu(z[src] + c + bm); agg[dst] += m
// ---------------------------------------------------------------------------
__global__ void __launch_bounds__(256, 2)
edge_msg_kernel(const int* __restrict__ eidx,
                const float* __restrict__ ef,
                const float* __restrict__ We,
                const float* __restrict__ be,
                const float* __restrict__ Wm_bot,
                const float* __restrict__ bm_l) {
    extern __shared__ char raw[];
    char* sb = (char*)(((uintptr_t)raw + 1023) & ~(uintptr_t)1023);
    int t = threadIdx.x;
    int wid = t >> 5;

#if USE_TC
    const uint32_t sb_u = smem_u32(sb);
    float* sbm = (float*)(sb + OFF_BM);
    float* sM  = (float*)(sb + OFF_SM);
    int* sSrcA[3] = {(int*)(sb + OFF_SRC), (int*)(sb + OFF_SRC + 512), (int*)(sb + OFF_SRC + 1024)};
    int* sDstA[3] = {(int*)(sb + OFF_DST), (int*)(sb + OFF_DST + 512), (int*)(sb + OFF_DST + 1024)};
    uint32_t tptr = sb_u + OFF_TPTR;
    uint32_t cmbA[3] = {sb_u + OFF_CMB0, sb_u + OFF_CMB1, sb_u + OFF_CMB2};
    uint32_t aoff[3] = {sb_u + OFF_A0, sb_u + OFF_A1, sb_u + OFF_A2};
    uint32_t mmb0 = sb_u + OFF_MMB0;
    uint32_t mmb1 = sb_u + OFF_MMB1;

    if (t < 64) sbm[t] = bm_l[t];

    // stage Wm_bot^T as fp16 hi/lo, SW128 (B operand: [N=64 rows][K=64])
    {
        int n = t & 63, kg = t >> 6;   // kg in 0..3
        for (int k2 = 0; k2 < 16; k2++) {
            int k = kg * 16 + k2;
            float w = Wm_bot[k * HID + n];
            __half wh = __float2half_rn(w);
            __half wl = __float2half_rn(w - __half2float(wh));
            uint32_t sw = SW128((uint32_t)(n * 128 + k * 2));
            *(unsigned short*)(sb + OFF_W_HI + sw) = *reinterpret_cast<unsigned short*>(&wh);
            *(unsigned short*)(sb + OFF_W_LO + sw) = *reinterpret_cast<unsigned short*>(&wl);
        }
    }

    if (t == 0) {
        MBARRIER_INIT(cmbA[0], 1); MBARRIER_INIT(cmbA[1], 1); MBARRIER_INIT(cmbA[2], 1);
        MBARRIER_INIT(mmb0, 1);    MBARRIER_INIT(mmb1, 1);
    }
    if (wid == 0) TCGEN05_ALLOC(tptr, 128);
    __syncthreads();
    uint32_t tmem;
    asm volatile("ld.shared.b32 %0, [%1];" : "=r"(tmem) : "r"(tptr));
    if (wid == 0) TCGEN05_RELINQ();
    const uint32_t tmem0 = tmem, tmem1 = tmem + 64;

    const uint64_t dW_hi = MAKE_SMEM_DESC(sb_u + OFF_W_HI);
    const uint64_t dW_lo = MAKE_SMEM_DESC(sb_u + OFF_W_LO);

    int eh = t >> 4, q = t & 15;        // 16 lanes per edge
    int lane = t & 31;
    int subp = wid & 3, half = wid >> 2;

    FENCE_PROXY_ASYNC();   // W-tile SIMT writes -> async proxy, once
    __syncthreads();

    const int base = (int)blockIdx.x, stride = (int)gridDim.x;
    int ntile = (base < N_TILES) ? ((N_TILES - 1 - base) / stride + 1) : 0;

    uint32_t cph[3] = {0, 0, 0};
    uint32_t mph0 = 0, mph1 = 0;

    // prologue: prefetch copies for tiles 0 and 1
    if (ntile > 0) {
        if (t == 0) {
            MBARRIER_EXPECT_TX(cmbA[0], EA_TILE_BYTES);
            CP_BULK_G2S(aoff[0],
                        (const void*)(g_eA + (size_t)base * EA_TILE_BYTES),
                        EA_TILE_BYTES, cmbA[0]);
        }
        if (t < 128) {
            sSrcA[0][t] = eidx[base * TILE_E + t];
            sDstA[0][t] = eidx[N_EDGES + base * TILE_E + t];
        }
    }
    if (ntile > 1) {
        int tl = base + stride;
        if (t == 0) {
            MBARRIER_EXPECT_TX(cmbA[1], EA_TILE_BYTES);
            CP_BULK_G2S(aoff[1],
                        (const void*)(g_eA + (size_t)tl * EA_TILE_BYTES),
                        EA_TILE_BYTES, cmbA[1]);
        }
        if (t < 128) {
            sSrcA[1][t] = eidx[tl * TILE_E + t];
            sDstA[1][t] = eidx[N_EDGES + tl * TILE_E + t];
        }
    }
    __syncthreads();

    // prologue MMA for tile 0 into tmem0
    if (ntile > 0 && wid == 0) {
        if (elect_one_pred()) {
            MBARRIER_WAIT_PARITY(cmbA[0], cph[0]); cph[0] ^= 1;
            uint64_t a = MAKE_SMEM_DESC(aoff[0]);
#pragma unroll
            for (int ks = 0; ks < 4; ks++) {
                uint64_t off = (uint64_t)(ks * 2);
                mma_f16_ss(tmem0, a + off, dW_hi + off, MMA_IDESC, ks > 0 ? 1u : 0u);
                mma_f16_ss(tmem0, a + off, dW_lo + off, MMA_IDESC, 1u);
            }
            TCGEN05_COMMIT(mmb0);
        }
    }

    for (int k = 0; k < ntile; k++) {
        int b = k % 3;

        // copy for tile k+2 (A[(k+2)%3] drained: MMA(k-1) waited in iter k-1)
        if (k + 2 < ntile) {
            int b2 = (k + 2) % 3;
            int tl = base + (k + 2) * stride;
            if (t == 0) {
                MBARRIER_EXPECT_TX(cmbA[b2], EA_TILE_BYTES);
                CP_BULK_G2S(aoff[b2],
                            (const void*)(g_eA + (size_t)tl * EA_TILE_BYTES),
                            EA_TILE_BYTES, cmbA[b2]);
            }
            if (t < 128) {
                sSrcA[b2][t] = eidx[tl * TILE_E + t];
                sDstA[b2][t] = eidx[N_EDGES + tl * TILE_E + t];
            }
        }

        // MMA for tile k+1 into the alternate accumulator (copy long done)
        if (k + 1 < ntile && wid == 0) {
            if (elect_one_pred()) {
                int b1 = (k + 1) % 3;
                MBARRIER_WAIT_PARITY(cmbA[b1], cph[b1]); cph[b1] ^= 1;
                uint64_t a = MAKE_SMEM_DESC(aoff[b1]);
                uint32_t tm = ((k + 1) & 1) ? tmem1 : tmem0;
#pragma unroll
                for (int ks = 0; ks < 4; ks++) {
                    uint64_t off = (uint64_t)(ks * 2);
                    mma_f16_ss(tm, a + off, dW_hi + off, MMA_IDESC, ks > 0 ? 1u : 0u);
                    mma_f16_ss(tm, a + off, dW_lo + off, MMA_IDESC, 1u);
                }
                TCGEN05_COMMIT(((k + 1) & 1) ? mmb1 : mmb0);
            }
        }

        // prefetch z[src] for tile k
        const int* mySrc = sSrcA[b];
        const int* myDst = sDstA[b];
        float4 zv[8];
#pragma unroll
        for (int pp = 0; pp < 8; pp++) {
            int e = pp * 16 + eh;
            zv[pp] = __ldg((const float4*)(g_z + (size_t)mySrc[e] * HID) + q);
        }

        // wait MMA(k) — issued one iteration ago, fast-path complete
        if (k & 1) { MBARRIER_WAIT_PARITY(mmb1, mph1); mph1 ^= 1; }
        else       { MBARRIER_WAIT_PARITY(mmb0, mph0); mph0 ^= 1; }
        TCGEN05_FENCE_AFTER();

        // stage TMEM -> sM with float4 STS (stride-68 rows)
        {
            uint32_t d[32];
            TCGEN05_LD_32X32B_X32(d, ((k & 1) ? tmem1 : tmem0) + half * 32);
            TCGEN05_WAIT_LD();
            TCGEN05_FENCE_BEFORE();
            float4* mp = (float4*)(sM + (subp * 32 + lane) * 68 + half * 32);
#pragma unroll
            for (int j = 0; j < 8; j++)
                mp[j] = make_float4(__uint_as_float(d[4 * j + 0]),
                                    __uint_as_float(d[4 * j + 1]),
                                    __uint_as_float(d[4 * j + 2]),
                                    __uint_as_float(d[4 * j + 3]));
        }
        __syncthreads();

        // coalesced epilogue: 16 lanes per edge cover 64 contiguous floats
#pragma unroll
        for (int pp = 0; pp < 8; pp++) {
            int e = pp * 16 + eh;
            int dst = myDst[e];
            float4 mv = *(const float4*)(sM + e * 68 + q * 4);
            float v0 = fmaxf(mv.x + zv[pp].x + sbm[q * 4 + 0], 0.f);
            float v1 = fmaxf(mv.y + zv[pp].y + sbm[q * 4 + 1], 0.f);
            float v2 = fmaxf(mv.z + zv[pp].z + sbm[q * 4 + 2], 0.f);
            float v3 = fmaxf(mv.w + zv[pp].w + sbm[q * 4 + 3], 0.f);
            red_add_v4(g_agg + (size_t)dst * HID + q * 4, v0, v1, v2, v3);
        }
        __syncthreads();   // protect sM/idx before next iteration
    }

    __syncthreads();
    if (wid == 0) TCGEN05_DEALLOC(tmem, 128);

#else  // ------------------- SIMT fallback path ----------------------------
    float* sE  = (float*)(sb + FOFF_E);
    float* sWm = (float*)(sb + FOFF_WM);
    float* sWe = (float*)(sb + FOFF_SWE);
    float* sbe = (float*)(sb + FOFF_BE);
    float* sbm = (float*)(sb + FOFF_BM);
    int*   sSrc = (int*)(sb + FOFF_SRC);
    int*   sDst = (int*)(sb + FOFF_DST);

    for (int i = t; i < D_EDGE * HID; i += 256) sWe[i] = We[i];
    if (t < 64) { sbe[t] = be[t]; sbm[t] = bm_l[t]; }
    {
        const float4* w4 = (const float4*)Wm_bot;
        float4* s4 = (float4*)sWm;
        for (int i = t; i < 1024; i += 256) s4[i] = w4[i];
    }

    int r = t >> 1, hf = t & 1;
    int tx = t & 15, ty = t >> 4;

    for (int tile = blockIdx.x; tile < N_TILES; tile += gridDim.x) {
        int eb = tile * TILE_E;
        if (t < 128) {
            sSrc[t] = eidx[eb + t];
            sDst[t] = eidx[N_EDGES + eb + t];
        }
        {
            const float4* e4 = (const float4*)(ef + (size_t)(eb + r) * D_EDGE);
            float4 e0 = __ldg(e4), e1 = __ldg(e4 + 1);
            float xf[8] = {e0.x, e0.y, e0.z, e0.w, e1.x, e1.y, e1.z, e1.w};
#pragma unroll
            for (int g = 0; g < 8; g++) {
                int c0 = hf * 32 + g * 4;
                float4 acc = *(const float4*)(sbe + c0);
#pragma unroll
                for (int k = 0; k < 8; k++) {
                    float4 wv = *(const float4*)(sWe + k * HID + c0);
                    acc.x += xf[k] * wv.x; acc.y += xf[k] * wv.y;
                    acc.z += xf[k] * wv.z; acc.w += xf[k] * wv.w;
                }
                acc.x = fmaxf(acc.x, 0.f); acc.y = fmaxf(acc.y, 0.f);
                acc.z = fmaxf(acc.z, 0.f); acc.w = fmaxf(acc.w, 0.f);
                *(float4*)(sE + r * 68 + c0) = acc;
            }
        }
        __syncthreads();

        float acc[8][4] = {};
        const float4* sW4 = (const float4*)sWm;
        const float4* sE4 = (const float4*)sE;
#pragma unroll 4
        for (int kq = 0; kq < 16; kq++) {
            float4 w0 = sW4[(4 * kq + 0) * 16 + tx];
            float4 w1 = sW4[(4 * kq + 1) * 16 + tx];
            float4 w2 = sW4[(4 * kq + 2) * 16 + tx];
            float4 w3 = sW4[(4 * kq + 3) * 16 + tx];
#pragma unroll
            for (int e8 = 0; e8 < 8; e8++) {
                float4 xv = sE4[(ty * 8 + e8) * 17 + kq];
                acc[e8][0] += xv.x * w0.x + xv.y * w1.x + xv.z * w2.x + xv.w * w3.x;
                acc[e8][1] += xv.x * w0.y + xv.y * w1.y + xv.z * w2.y + xv.w * w3.y;
                acc[e8][2] += xv.x * w0.z + xv.y * w1.z + xv.z * w2.z + xv.w * w3.z;
                acc[e8][3] += xv.x * w0.w + xv.y * w1.w + xv.z * w2.w + xv.w * w3.w;
            }
        }
        float b0 = sbm[tx * 4], b1 = sbm[tx * 4 + 1], b2 = sbm[tx * 4 + 2], b3 = sbm[tx * 4 + 3];
#pragma unroll
        for (int e8 = 0; e8 < 8; e8++) {
            int e = ty * 8 + e8;
            int src = sSrc[e], dst = sDst[e];
            float4 zv = __ldg((const float4*)(g_z + (size_t)src * HID) + tx);
            float v0 = fmaxf(acc[e8][0] + zv.x + b0, 0.f);
            float v1 = fmaxf(acc[e8][1] + zv.y + b1, 0.f);
            float v2 = fmaxf(acc[e8][2] + zv.z + b2, 0.f);
            float v3 = fmaxf(acc[e8][3] + zv.w + b3, 0.f);
            red_add_v4(g_agg + (size_t)dst * HID + tx * 4, v0, v1, v2, v3);
        }
        __syncthreads();
    }
#endif
}

// ---------------------------------------------------------------------------
// h = relu(NF @ Wn + bn);  z = h @ Wm_top[layer 0]   (fused)
__global__ void __launch_bounds__(256)
node_proj_kernel(const float* __restrict__ nf,
                 const float* __restrict__ Wn,
                 const float* __restrict__ bn,
                 const float* __restrict__ Wm_top) {
    __shared__ float sWn[D_NODE * HID];
    __shared__ float sbn[HID];
    __shared__ float sWm[HID * HID];
    __shared__ float sX[64 * 68];
    int t = threadIdx.x;
    int nb = blockIdx.x * 64;

    for (int i = t; i < D_NODE * HID; i += 256) sWn[i] = Wn[i];
    if (t < HID) sbn[t] = bn[t];
    {
        const float4* w4 = (const float4*)Wm_top;
        float4* s4 = (float4*)sWm;
        for (int i = t; i < 1024; i += 256) s4[i] = w4[i];
    }
    __syncthreads();

    {
        int r = t >> 2, cg = (t & 3) * 16;
        int node = nb + r;
        float xv[D_NODE];
#pragma unroll
        for (int k = 0; k < D_NODE; k++) xv[k] = 0.f;
        if (node < N_NODES) {
            const float4* xp = (const float4*)(nf + (size_t)node * D_NODE);
            float4 x0 = xp[0], x1 = xp[1], x2 = xp[2], x3 = xp[3];
            xv[0] = x0.x; xv[1] = x0.y; xv[2] = x0.z; xv[3] = x0.w;
            xv[4] = x1.x; xv[5] = x1.y; xv[6] = x1.z; xv[7] = x1.w;
            xv[8] = x2.x; xv[9] = x2.y; xv[10] = x2.z; xv[11] = x2.w;
            xv[12] = x3.x; xv[13] = x3.y; xv[14] = x3.z; xv[15] = x3.w;
        }
        float hv[16];
#pragma unroll
        for (int j = 0; j < 16; j++) {
            int col = cg + j;
            float a = sbn[col];
#pragma unroll
            for (int k = 0; k < D_NODE; k++) a += xv[k] * sWn[k * HID + col];
            hv[j] = fmaxf(a, 0.f);
            sX[r * 68 + col] = hv[j];
        }
        if (node < N_NODES) {
            float4* o = (float4*)(g_h + (size_t)node * HID + cg);
            o[0] = make_float4(hv[0], hv[1], hv[2], hv[3]);
            o[1] = make_float4(hv[4], hv[5], hv[6], hv[7]);
            o[2] = make_float4(hv[8], hv[9], hv[10], hv[11]);
            o[3] = make_float4(hv[12], hv[13], hv[14], hv[15]);
        }
    }
    __syncthreads();

    int tx = t & 15, ty = t >> 4;
    float acc[4][4] = {};
    const float4* sW4 = (const float4*)sWm;
    const float4* sX4 = (const float4*)sX;
#pragma unroll 4
    for (int kq = 0; kq < 16; kq++) {
        float4 w0 = sW4[(4 * kq + 0) * 16 + tx];
        float4 w1 = sW4[(4 * kq + 1) * 16 + tx];
        float4 w2 = sW4[(4 * kq + 2) * 16 + tx];
        float4 w3 = sW4[(4 * kq + 3) * 16 + tx];
#pragma unroll
        for (int ee = 0; ee < 4; ee++) {
            float4 xv = sX4[(ty * 4 + ee) * 17 + kq];
            acc[ee][0] += xv.x * w0.x + xv.y * w1.x + xv.z * w2.x + xv.w * w3.x;
            acc[ee][1] += xv.x * w0.y + xv.y * w1.y + xv.z * w2.y + xv.w * w3.y;
            acc[ee][2] += xv.x * w0.z + xv.y * w1.z + xv.z * w2.z + xv.w * w3.z;
            acc[ee][3] += xv.x * w0.w + xv.y * w1.w + xv.z * w2.w + xv.w * w3.w;
        }
    }
#pragma unroll
    for (int ee = 0; ee < 4; ee++) {
        int node = nb + ty * 4 + ee;
        if (node >= N_NODES) continue;
        *(float4*)(g_z + (size_t)node * HID + tx * 4) =
            make_float4(acc[ee][0], acc[ee][1], acc[ee][2], acc[ee][3]);
    }
}

// ---------------------------------------------------------------------------
__global__ void zero_agg_kernel() {
    int i = blockIdx.x * blockDim.x + threadIdx.x;
    float4* p = (float4*)g_agg;
    const int n4 = N_NODES * HID / 4;
    for (int j = i; j < n4; j += gridDim.x * blockDim.x)
        p[j] = make_float4(0.f, 0.f, 0.f, 0.f);
    if (blockIdx.x == 0 && threadIdx.x < HID) g_gsum[threadIdx.x] = 0.f;
}

// ---------------------------------------------------------------------------
// 128-node tiles, 2 CTAs/SM: h = relu([h, agg] @ Wu_l + bu_l) + h ; zeroes agg;
// optional z = h_new @ Wm_next (layers 0..N-2) OR fused gsum (last layer).
__global__ void __launch_bounds__(256, 2)
node_update_kernel(const float* __restrict__ Wu_l,
                   const float* __restrict__ bu_l,
                   const float* __restrict__ Wm_next,
                   int compute_z) {
    extern __shared__ float sm[];
    float* sW = sm;            // 8192 floats
    float* sX = sm + 8192;     // 128 x 132 = 16896 floats
    float* sb = sm + 25088;    // 64 floats
    int t = threadIdx.x;
    int nb = blockIdx.x * 128;

    {
        const float4* w4 = (const float4*)Wu_l;
        float4* s4 = (float4*)sW;
        for (int i = t; i < 2048; i += 256) s4[i] = w4[i];
        if (t < 64) sb[t] = bu_l[t];
    }
    const float4 z4 = make_float4(0.f, 0.f, 0.f, 0.f);
#pragma unroll
    for (int i = 0; i < 8; i++) {
        int id = t + 256 * i;        // 2048 tasks = 128 rows x 16 quads
        int r = id >> 4, qq = id & 15;
        int node = nb + r;
        float4 vh = z4, va = z4;
        if (node < N_NODES) {
            vh = *(const float4*)(g_h + (size_t)node * HID + qq * 4);
            va = *(const float4*)(g_agg + (size_t)node * HID + qq * 4);
            *(float4*)(g_agg + (size_t)node * HID + qq * 4) = z4;
        }
        *(float4*)(sX + r * 132 + qq * 4) = vh;
        *(float4*)(sX + r * 132 + 64 + qq * 4) = va;
    }
    __syncthreads();

    int tx = t & 15, ty = t >> 4;
    float acc[8][4] = {};
    const float4* sW4 = (const float4*)sW;
    const float4* sX4 = (const float4*)sX;
#pragma unroll 4
    for (int kq = 0; kq < 32; kq++) {
        float4 w0 = sW4[(4 * kq + 0) * 16 + tx];
        float4 w1 = sW4[(4 * kq + 1) * 16 + tx];
        float4 w2 = sW4[(4 * kq + 2) * 16 + tx];
        float4 w3 = sW4[(4 * kq + 3) * 16 + tx];
#pragma unroll
        for (int ee = 0; ee < 8; ee++) {
            float4 xv = sX4[(ty * 8 + ee) * 33 + kq];
            acc[ee][0] += xv.x * w0.x + xv.y * w1.x + xv.z * w2.x + xv.w * w3.x;
            acc[ee][1] += xv.x * w0.y + xv.y * w1.y + xv.z * w2.y + xv.w * w3.y;
            acc[ee][2] += xv.x * w0.z + xv.y * w1.z + xv.z * w2.z + xv.w * w3.z;
            acc[ee][3] += xv.x * w0.w + xv.y * w1.w + xv.z * w2.w + xv.w * w3.w;
        }
    }
    __syncthreads();   // all GEMM reads of sX/sW complete before overwrite

    float csum[4] = {0.f, 0.f, 0.f, 0.f};
#pragma unroll
    for (int ee = 0; ee < 8; ee++) {
        int r = ty * 8 + ee;
        int node = nb + r;
#pragma unroll
        for (int c = 0; c < 4; c++) {
            int col = tx * 4 + c;
            float hold = sX[r * 132 + col];
            float hn = fmaxf(acc[ee][c] + sb[col], 0.f) + hold;
            sX[r * 132 + col] = hn;
            if (node < N_NODES) {
                g_h[(size_t)node * HID + col] = hn;
                if (!compute_z) csum[c] += hn;
            }
        }
    }

    if (compute_z) {
        __syncthreads();
        {
            const float4* w4 = (const float4*)Wm_next;
            float4* s4 = (float4*)sW;
            for (int i = t; i < 1024; i += 256) s4[i] = w4[i];
        }
        __syncthreads();
        float acz[8][4] = {};
#pragma unroll 4
        for (int kq = 0; kq < 16; kq++) {
            float4 w0 = sW4[(4 * kq + 0) * 16 + tx];
            float4 w1 = sW4[(4 * kq + 1) * 16 + tx];
            float4 w2 = sW4[(4 * kq + 2) * 16 + tx];
            float4 w3 = sW4[(4 * kq + 3) * 16 + tx];
#pragma unroll
            for (int ee = 0; ee < 8; ee++) {
                float4 xv = sX4[(ty * 8 + ee) * 33 + kq];
                acz[ee][0] += xv.x * w0.x + xv.y * w1.x + xv.z * w2.x + xv.w * w3.x;
                acz[ee][1] += xv.x * w0.y + xv.y * w1.y + xv.z * w2.y + xv.w * w3.y;
                acz[ee][2] += xv.x * w0.z + xv.y * w1.z + xv.z * w2.z + xv.w * w3.z;
                acz[ee][3] += xv.x * w0.w + xv.y * w1.w + xv.z * w2.w + xv.w * w3.w;
            }
        }
#pragma unroll
        for (int ee = 0; ee < 8; ee++) {
            int node = nb + ty * 8 + ee;
            if (node >= N_NODES) continue;
            *(float4*)(g_z + (size_t)node * HID + tx * 4) =
                make_float4(acz[ee][0], acz[ee][1], acz[ee][2], acz[ee][3]);
        }
    } else {
        // fused gsum: column sums of h_new for the graph embedding
        __syncthreads();
        if (t < 64) sW[t] = 0.f;
        __syncthreads();
#pragma unroll
        for (int c = 0; c < 4; c++) atomicAdd(&sW[tx * 4 + c], csum[c]);
        __syncthreads();
        if (t < 64) atomicAdd(&g_gsum[t], sW[t]);
    }
}

// ---------------------------------------------------------------------------
// scores
__global__ void __launch_bounds__(256)
score_kernel(const int* __restrict__ od,
             const float* __restrict__ Ws1, const float* __restrict__ bs1,
             const float* __restrict__ Ws2, const float* __restrict__ bs2,
             float* __restrict__ out) {
    extern __shared__ float sm[];
    float* sW  = sm;
    float* sX  = sm + 8192;
    float* sb  = sm + 16640;
    float* sw2 = sm + 16704;
    int*   sA  = (int*)(sm + 16768);
    int*   sB  = (int*)(sm + 16832);
    int t = threadIdx.x;
    int pb = blockIdx.x * 64;

    {
        const float4* w4 = (const float4*)Ws1;
        float4* s4 = (float4*)sW;
        for (int i = t; i < 2048; i += 256) s4[i] = w4[i];
        if (t < 64) {
            sb[t] = bs1[t];
            sw2[t] = Ws2[t];
            int p = pb + t;
            sA[t] = (p < N_OD) ? od[p] : 0;
            sB[t] = (p < N_OD) ? od[N_OD + p] : 0;
        }
    }
    __syncthreads();
#pragma unroll
    for (int i = 0; i < 4; i++) {
        int id = t + 256 * i;
        int r = id >> 4, q = id & 15;
        *(float4*)(sX + r * 132 + q * 4) =
            *(const float4*)(g_h + (size_t)sA[r] * HID + q * 4);
        *(float4*)(sX + r * 132 + 64 + q * 4) =
            *(const float4*)(g_h + (size_t)sB[r] * HID + q * 4);
    }
    __syncthreads();

    int tx = t & 15, ty = t >> 4;
    float acc[4][4] = {};
    const float4* sW4 = (const float4*)sW;
    const float4* sX4 = (const float4*)sX;
#pragma unroll 4
    for (int kq = 0; kq < 32; kq++) {
        float4 w0 = sW4[(4 * kq + 0) * 16 + tx];
        float4 w1 = sW4[(4 * kq + 1) * 16 + tx];
        float4 w2 = sW4[(4 * kq + 2) * 16 + tx];
        float4 w3 = sW4[(4 * kq + 3) * 16 + tx];
#pragma unroll
        for (int ee = 0; ee < 4; ee++) {
            float4 xv = sX4[(ty * 4 + ee) * 33 + kq];
            acc[ee][0] += xv.x * w0.x + xv.y * w1.x + xv.z * w2.x + xv.w * w3.x;
            acc[ee][1] += xv.x * w0.y + xv.y * w1.y + xv.z * w2.y + xv.w * w3.y;
            acc[ee][2] += xv.x * w0.z + xv.y * w1.z + xv.z * w2.z + xv.w * w3.z;
            acc[ee][3] += xv.x * w0.w + xv.y * w1.w + xv.z * w2.w + xv.w * w3.w;
        }
    }
    float part[4];
#pragma unroll
    for (int ee = 0; ee < 4; ee++) {
        float s = 0.f;
#pragma unroll
        for (int c = 0; c < 4; c++) {
            int col = tx * 4 + c;
            s += fmaxf(acc[ee][c] + sb[col], 0.f) * sw2[col];
        }
        part[ee] = s;
    }
#pragma unroll
    for (int off = 8; off >= 1; off >>= 1) {
#pragma unroll
        for (int ee = 0; ee < 4; ee++)
            part[ee] += __shfl_xor_sync(0xffffffffu, part[ee], off);
    }
    if (tx == 0) {
        float b2 = bs2[0];
#pragma unroll
        for (int ee = 0; ee < 4; ee++) {
            int p = pb + ty * 4 + ee;
            if (p < N_OD) out[p] = part[ee] + b2;
        }
    }
}

// ---------------------------------------------------------------------------
__global__ void khead_kernel(const float* __restrict__ ts,
                             const float* __restrict__ Wk1, const float* __restrict__ bk1,
                             const float* __restrict__ Wk2, const float* __restrict__ bk2,
                             const float* __restrict__ Wk3, const float* __restrict__ bk3,
                             float* __restrict__ out, int out_size) {
    __shared__ float x[68];
    __shared__ float h1[32];
    __shared__ float h2[16];
    int t = threadIdx.x;
    if (t < 64) x[t] = g_gsum[t] * (1.0f / (float)N_NODES);
    if (t < 4)  x[64 + t] = ts[t];
    __syncthreads();
    if (t < 32) {
        float a = bk1[t];
        for (int i = 0; i < 68; i++) a += x[i] * Wk1[i * 32 + t];
        h1[t] = fmaxf(a, 0.f);
    }
    __syncthreads();
    if (t < 16) {
        float a = bk2[t];
        for (int i = 0; i < 32; i++) a += h1[i] * Wk2[i * 16 + t];
        h2[t] = fmaxf(a, 0.f);
    }
    __syncthreads();
    if (t == 0) {
        float a = bk3[0];
        for (int i = 0; i < 16; i++) a += h2[i] * Wk3[i];
        float sig = 1.f / (1.f + expf(-a));
        out[out_size - 1] = 1.0f + sig * 49.0f;
    }
}

// ---------------------------------------------------------------------------
extern "C" void kernel_launch(void* const* d_in, const int* in_sizes, int n_in,
                              void* d_out, int out_size) {
    const float* nf   = (const float*)d_in[0];
    const int*   eidx = (const int*)d_in[1];
    const float* ef   = (const float*)d_in[2];
    const int*   od   = (const int*)d_in[3];
    const float* ts   = (const float*)d_in[4];
    const float* Wn   = (const float*)d_in[5];
    const float* bn   = (const float*)d_in[6];
    const float* We   = (const float*)d_in[7];
    const float* be   = (const float*)d_in[8];
    const float* Wm   = (const float*)d_in[9];
    const float* bm   = (const float*)d_in[10];
    const float* Wu   = (const float*)d_in[11];
    const float* bu   = (const float*)d_in[12];
    const float* Ws1  = (const float*)d_in[13];
    const float* bs1  = (const float*)d_in[14];
    const float* Ws2  = (const float*)d_in[15];
    const float* bs2  = (const float*)d_in[16];
    const float* Wk1  = (const float*)d_in[17];
    const float* bk1  = (const float*)d_in[18];
    const float* Wk2  = (const float*)d_in[19];
    const float* bk2  = (const float*)d_in[20];
    const float* Wk3  = (const float*)d_in[21];
    const float* bk3  = (const float*)d_in[22];
    float* out = (float*)d_out;

    const int SMEM_UPD   = 100864;
    const int SMEM_SCORE = 67584;
    cudaFuncSetAttribute(edge_msg_kernel, cudaFuncAttributeMaxDynamicSharedMemorySize, SMEM_EDGE_BYTES);
    cudaFuncSetAttribute(node_update_kernel, cudaFuncAttributeMaxDynamicSharedMemorySize, SMEM_UPD);
    cudaFuncSetAttribute(score_kernel, cudaFuncAttributeMaxDynamicSharedMemorySize, SMEM_SCORE);

    // one-time: e tiles in pre-swizzled fp16 layout
    edge_e_kernel<<<N_TILES, 256>>>(ef, We, be);
    // h + z(layer0) fused
    node_proj_kernel<<<(N_NODES + 63) / 64, 256>>>(nf, Wn, bn, Wm);
    zero_agg_kernel<<<3125, 256>>>();

    for (int l = 0; l < N_LAYERS; l++) {
        const float* Wm_l = Wm + (size_t)l * 2 * HID * HID;
        const float* Wm_next = Wm + (size_t)(l + 1 < N_LAYERS ? l + 1 : l) * 2 * HID * HID;
        edge_msg_kernel<<<296, 256, SMEM_EDGE_BYTES>>>(
            eidx, ef, We, be, Wm_l + (size_t)HID * HID, bm + (size_t)l * HID);
        node_update_kernel<<<(N_NODES + 127) / 128, 256, SMEM_UPD>>>(
            Wu + (size_t)l * 2 * HID * HID, bu + (size_t)l * HID,
            Wm_next, l + 1 < N_LAYERS ? 1 : 0);
    }

    khead_kernel<<<1, 64>>>(ts, Wk1, bk1, Wk2, bk2, Wk3, bk3, out, out_size);
    score_kernel<<<(N_OD + 63) / 64, 256, SMEM_SCORE>>>(od, Ws1, bs1, Ws2, bs2, out);
}

// round 14
// speedup vs baseline: 1.1562x; 1.1562x over previous
#include <cuda_runtime.h>
#include <cuda_bf16.h>
#include <cuda_fp16.h>
#include <math.h>
#include <stdint.h>

#define N_NODES 50000
#define N_EDGES 1200000
#define N_OD    10000
#define D_NODE  16
#define D_EDGE  8
#define HID     64
#define N_LAYERS 3
#define TILE_E  128
#define N_TILES (N_EDGES / TILE_E)   // 9375 exactly
#define EA_TILE_BYTES 16384          // fp16 e tile: 128 rows x 128B

#if defined(__CUDA_ARCH__) && (defined(__CUDA_ARCH_FEAT_SM103_ALL) || defined(__CUDA_ARCH_FEAT_SM100_ALL))
#define USE_TC 1
#else
#define USE_TC 0
#endif

// persistent scratch
__device__ float g_h[N_NODES * HID];
__device__ float g_agg[N_NODES * HID];
__device__ float g_z[N_NODES * HID];     // z = h @ Wm_top (per layer)
__device__ float g_gsum[HID];
// layer-invariant edge features, fp16, pre-swizzled A-tile layout
__device__ __align__(1024) char g_eA[(size_t)N_TILES * EA_TILE_BYTES];

// ---------------------------------------------------------------------------
// helpers
// ---------------------------------------------------------------------------
__device__ __forceinline__ void red_add_v4(float* p, float a, float b, float c, float d) {
    asm volatile("red.global.add.v4.f32 [%0], {%1, %2, %3, %4};"
                 :: "l"(p), "f"(a), "f"(b), "f"(c), "f"(d) : "memory");
}

#if USE_TC
__device__ __forceinline__ uint32_t elect_one_pred() {
    uint32_t pred;
    asm volatile(
        "{\n\t.reg .pred p;\n\t"
        "elect.sync _|p, 0xFFFFFFFF;\n\t"
        "selp.b32 %0, 1, 0, p;\n\t}"
        : "=r"(pred));
    return pred;
}
#endif

__device__ __forceinline__ uint32_t smem_u32(const void* p) {
    uint32_t a;
    asm("{ .reg .u64 t; cvta.to.shared.u64 t, %1; cvt.u32.u64 %0, t; }"
        : "=r"(a) : "l"(p));
    return a;
}
#define SW128(o) ((o) ^ (((o) >> 3) & 0x70))

static constexpr uint64_t SMEM_DESC_BASE_SW128 =
    (uint64_t(2)  << 61) | (uint64_t(1) << 46) | (uint64_t(64) << 32) | (uint64_t(1) << 16);
#define MAKE_SMEM_DESC(base_addr) \
    (SMEM_DESC_BASE_SW128 | ((uint64_t)((base_addr) >> 4) & 0x3FFF))

#if USE_TC
#define TCGEN05_ALLOC(smem_result_addr, nCols) \
    asm volatile("tcgen05.alloc.cta_group::1.sync.aligned.shared::cta.b32 [%0], %1;" \
        :: "r"((uint32_t)(smem_result_addr)), "r"((uint32_t)(nCols)) : "memory")
#define TCGEN05_DEALLOC(tmem_addr, nCols) \
    asm volatile("tcgen05.dealloc.cta_group::1.sync.aligned.b32 %0, %1;" \
        :: "r"(tmem_addr), "r"((uint32_t)(nCols)))
#define TCGEN05_RELINQ() \
    asm volatile("tcgen05.relinquish_alloc_permit.cta_group::1.sync.aligned;")
#define TCGEN05_COMMIT(mbar_smem_addr) \
    asm volatile("tcgen05.commit.cta_group::1.mbarrier::arrive::one.shared::cluster.b64 [%0];" \
        :: "r"((uint32_t)(mbar_smem_addr)) : "memory")
#define TCGEN05_WAIT_LD() \
    asm volatile("tcgen05.wait::ld.sync.aligned;" ::: "memory")
#define TCGEN05_FENCE_BEFORE() \
    asm volatile("tcgen05.fence::before_thread_sync;" ::: "memory")
#define TCGEN05_FENCE_AFTER() \
    asm volatile("tcgen05.fence::after_thread_sync;" ::: "memory")
#define FENCE_PROXY_ASYNC() \
    asm volatile("fence.proxy.async.shared::cta;" ::: "memory")
#define MBARRIER_INIT(mbar, count) \
    asm volatile("mbarrier.init.shared.b64 [%0], %1;" \
        :: "r"((uint32_t)(mbar)), "r"((uint32_t)(count)) : "memory")
#define MBARRIER_EXPECT_TX(mbar, bytes) \
    asm volatile("mbarrier.arrive.expect_tx.shared.b64 _, [%0], %1;" \
        :: "r"((uint32_t)(mbar)), "r"((uint32_t)(bytes)) : "memory")
#define CP_BULK_G2S(dst, src, bytes, mbar) \
    asm volatile("cp.async.bulk.shared::cluster.global.mbarrier::complete_tx::bytes [%0], [%1], %2, [%3];" \
        :: "r"((uint32_t)(dst)), "l"(src), "r"((uint32_t)(bytes)), "r"((uint32_t)(mbar)) : "memory")
#define MBARRIER_WAIT_PARITY(mbar_smem_addr, phase_parity) do { \
    uint32_t _mbar = (uint32_t)(mbar_smem_addr); \
    uint32_t _parity = (uint32_t)(phase_parity); \
    uint32_t _done; \
    asm volatile( \
        "{\n\t.reg .pred p;\n\t" \
        "mbarrier.try_wait.parity.acquire.cta.shared::cta.b64 p, [%1], %2;\n\t" \
        "selp.b32 %0, 1, 0, p;\n\t}" \
        : "=r"(_done) : "r"(_mbar), "r"(_parity) : "memory"); \
    if (!_done) { \
        asm volatile( \
            "{\n\t.reg .pred P1;\n\t" \
            "WAIT_LOOP_%=:\n\t" \
            "mbarrier.try_wait.parity.acquire.cta.shared::cta.b64 P1, [%0], %1, 0x989680;\n\t" \
            "@P1 bra.uni WAIT_DONE_%=;\n\t" \
            "bra.uni WAIT_LOOP_%=;\n\t" \
            "WAIT_DONE_%=:\n\t}" \
            :: "r"(_mbar), "r"(_parity) : "memory"); \
    } \
} while(0)

#define TCGEN05_LD_32X32B_X32(r, tmem_addr) \
    asm volatile( \
        "tcgen05.ld.sync.aligned.32x32b.x32.b32 " \
        "{%0, %1, %2, %3, %4, %5, %6, %7, " \
        " %8, %9, %10, %11, %12, %13, %14, %15, " \
        " %16, %17, %18, %19, %20, %21, %22, %23, " \
        " %24, %25, %26, %27, %28, %29, %30, %31}, [%32];" \
        : "=r"((r)[0]),  "=r"((r)[1]),  "=r"((r)[2]),  "=r"((r)[3]), \
          "=r"((r)[4]),  "=r"((r)[5]),  "=r"((r)[6]),  "=r"((r)[7]), \
          "=r"((r)[8]),  "=r"((r)[9]),  "=r"((r)[10]), "=r"((r)[11]), \
          "=r"((r)[12]), "=r"((r)[13]), "=r"((r)[14]), "=r"((r)[15]), \
          "=r"((r)[16]), "=r"((r)[17]), "=r"((r)[18]), "=r"((r)[19]), \
          "=r"((r)[20]), "=r"((r)[21]), "=r"((r)[22]), "=r"((r)[23]), \
          "=r"((r)[24]), "=r"((r)[25]), "=r"((r)[26]), "=r"((r)[27]), \
          "=r"((r)[28]), "=r"((r)[29]), "=r"((r)[30]), "=r"((r)[31]) \
        : "r"(tmem_addr))

__device__ __forceinline__ void mma_f16_ss(uint32_t d_tmem, uint64_t a_desc,
                                           uint64_t b_desc, uint32_t idesc,
                                           uint32_t acc) {
    asm volatile(
        "{\n\t.reg .pred p;\n\t"
        "setp.ne.u32 p, %5, 0;\n\t"
        "tcgen05.mma.cta_group::1.kind::f16 [%0], %1, %2, %3, {%4, %4, %4, %4}, p;\n\t"
        "}"
        :: "r"(d_tmem), "l"(a_desc), "l"(b_desc), "r"(idesc), "r"(0u), "r"(acc)
        : "memory");
}
#endif // USE_TC

// idesc: D=F32, A=FP16, B=FP16, N=64, M=128
#define MMA_IDESC 0x08100010u

// tensor-path smem byte offsets (from 1024-aligned base) — single fp16 A buf,
// round-11 late-prefetch structure
#define OFF_A    0        // 16KB
#define OFF_W_HI 16384    // 8KB
#define OFF_W_LO 24576    // 8KB
#define OFF_SM   32768    // 128 x 68 floats = 34816
#define OFF_BM   67584    // 64 floats
#define OFF_SRC0 67840    // 128 ints
#define OFF_SRC1 68352
#define OFF_DST0 68864
#define OFF_DST1 69376
#define OFF_TPTR 69888
#define OFF_CMB  69896
#define OFF_MMB  69904
// fallback-path smem offsets
#define FOFF_E    0       // 128 x 68 floats = 34816B
#define FOFF_WM   34816   // 64 x 64 floats = 16384B
#define FOFF_SWE  51200
#define FOFF_BE   53248
#define FOFF_BM   53504
#define FOFF_SRC  53760
#define FOFF_DST  54272
#define SMEM_EDGE_BYTES 71936

// ---------------------------------------------------------------------------
// One-time: e = relu(EF @ We + be), fp16, pre-swizzled A-tile layout.
// ---------------------------------------------------------------------------
__global__ void __launch_bounds__(256)
edge_e_kernel(const float* __restrict__ ef,
              const float* __restrict__ We,
              const float* __restrict__ be) {
    __shared__ float sWe[D_EDGE * HID];
    __shared__ float sbe[HID];
    int t = threadIdx.x;
    for (int i = t; i < D_EDGE * HID; i += 256) sWe[i] = We[i];
    if (t < 64) sbe[t] = be[t];
    __syncthreads();

    int tile = blockIdx.x;
    int eb = tile * TILE_E;
    int r = t >> 1, hf = t & 1;
    char* a_tile = g_eA + (size_t)tile * EA_TILE_BYTES;

    const float4* e4 = (const float4*)(ef + (size_t)(eb + r) * D_EDGE);
    float4 e0 = __ldg(e4), e1 = __ldg(e4 + 1);
    float xf[8] = {e0.x, e0.y, e0.z, e0.w, e1.x, e1.y, e1.z, e1.w};
#pragma unroll
    for (int g = 0; g < 8; g++) {
        int c0 = hf * 32 + g * 4;
        float4 acc = *(const float4*)(sbe + c0);
#pragma unroll
        for (int k = 0; k < 8; k++) {
            float4 wv = *(const float4*)(sWe + k * HID + c0);
            acc.x += xf[k] * wv.x; acc.y += xf[k] * wv.y;
            acc.z += xf[k] * wv.z; acc.w += xf[k] * wv.w;
        }
        acc.x = fmaxf(acc.x, 0.f); acc.y = fmaxf(acc.y, 0.f);
        acc.z = fmaxf(acc.z, 0.f); acc.w = fmaxf(acc.w, 0.f);
        __half2 p0 = __floats2half2_rn(acc.x, acc.y);
        __half2 p1 = __floats2half2_rn(acc.z, acc.w);
        uint2 v;
        v.x = *reinterpret_cast<uint32_t*>(&p0);
        v.y = *reinterpret_cast<uint32_t*>(&p1);
        uint32_t sw = SW128((uint32_t)(r * 128 + c0 * 2));
        *(uint2*)(a_tile + sw) = v;
    }
}

// ---------------------------------------------------------------------------
// Edge message kernel (persistent, single fp16 A buffer, 2 CTAs/SM, LATE
// prefetch — round-11 structure): the next tile's copy is issued right after
// the MMA drains A (post-mmb), overlapping the copy with LDTM + epilogue.
//   c = e @ Wm_bot (tcgen05 fp16); m = relu(z[src] + c + bm); agg[dst] += m
// ---------------------------------------------------------------------------
__global__ void __launch_bounds__(256, 2)
edge_msg_kernel(const int* __restrict__ eidx,
                const float* __restrict__ ef,
                const float* __restrict__ We,
                const float* __restrict__ be,
                const float* __restrict__ Wm_bot,
                const float* __restrict__ bm_l) {
    extern __shared__ char raw[];
    char* sb = (char*)(((uintptr_t)raw + 1023) & ~(uintptr_t)1023);
    int t = threadIdx.x;
    int wid = t >> 5;

#if USE_TC
    const uint32_t sb_u = smem_u32(sb);
    float* sbm = (float*)(sb + OFF_BM);
    float* sM  = (float*)(sb + OFF_SM);
    int* sSrcA[2] = {(int*)(sb + OFF_SRC0), (int*)(sb + OFF_SRC1)};
    int* sDstA[2] = {(int*)(sb + OFF_DST0), (int*)(sb + OFF_DST1)};
    uint32_t tptr = sb_u + OFF_TPTR;
    uint32_t cmb  = sb_u + OFF_CMB;
    uint32_t mmb  = sb_u + OFF_MMB;

    if (t < 64) sbm[t] = bm_l[t];

    // stage Wm_bot^T as fp16 hi/lo, SW128 (B operand: [N=64 rows][K=64])
    {
        int n = t & 63, kg = t >> 6;   // kg in 0..3
        for (int k2 = 0; k2 < 16; k2++) {
            int k = kg * 16 + k2;
            float w = Wm_bot[k * HID + n];
            __half wh = __float2half_rn(w);
            __half wl = __float2half_rn(w - __half2float(wh));
            uint32_t sw = SW128((uint32_t)(n * 128 + k * 2));
            *(unsigned short*)(sb + OFF_W_HI + sw) = *reinterpret_cast<unsigned short*>(&wh);
            *(unsigned short*)(sb + OFF_W_LO + sw) = *reinterpret_cast<unsigned short*>(&wl);
        }
    }

    if (t == 0) { MBARRIER_INIT(cmb, 1); MBARRIER_INIT(mmb, 1); }
    if (wid == 0) TCGEN05_ALLOC(tptr, 64);
    __syncthreads();
    uint32_t tmem;
    asm volatile("ld.shared.b32 %0, [%1];" : "=r"(tmem) : "r"(tptr));
    if (wid == 0) TCGEN05_RELINQ();

    const uint64_t dA    = MAKE_SMEM_DESC(sb_u + OFF_A);
    const uint64_t dW_hi = MAKE_SMEM_DESC(sb_u + OFF_W_HI);
    const uint64_t dW_lo = MAKE_SMEM_DESC(sb_u + OFF_W_LO);

    int eh = t >> 4, q = t & 15;        // 16 lanes per edge
    int lane = t & 31;
    int subp = wid & 3, half = wid >> 2;

    FENCE_PROXY_ASYNC();   // W-tile SIMT writes -> async proxy, once
    __syncthreads();

    uint32_t cph = 0, mph = 0;
    int tile = (int)blockIdx.x;
    const int stride = (int)gridDim.x;
    int pi = 0;

    // prologue: copy tile0 into A, load idx into buf0
    if (tile < N_TILES) {
        if (t == 0) {
            MBARRIER_EXPECT_TX(cmb, EA_TILE_BYTES);
            CP_BULK_G2S(sb_u + OFF_A,
                        (const void*)(g_eA + (size_t)tile * EA_TILE_BYTES),
                        EA_TILE_BYTES, cmb);
        }
        if (t < 128) {
            sSrcA[0][t] = eidx[tile * TILE_E + t];
            sDstA[0][t] = eidx[N_EDGES + tile * TILE_E + t];
        }
    }
    __syncthreads();

    for (; tile < N_TILES; tile += stride) {
        int nt = tile + stride;
        bool hn = nt < N_TILES;
        int ni = 1 - pi;

        // elected thread: wait current copy, issue 8 MMA dispatches, commit
        if (wid == 0) {
            if (elect_one_pred()) {
                MBARRIER_WAIT_PARITY(cmb, cph); cph ^= 1;
#pragma unroll
                for (int ks = 0; ks < 4; ks++) {
                    uint64_t off = (uint64_t)(ks * 2);
                    mma_f16_ss(tmem, dA + off, dW_hi + off, MMA_IDESC, ks > 0 ? 1u : 0u);
                    mma_f16_ss(tmem, dA + off, dW_lo + off, MMA_IDESC, 1u);
                }
                TCGEN05_COMMIT(mmb);
            }
        }

        // prefetch z[src] + next idx (both independent of MMA)
        const int* mySrc = sSrcA[pi];
        const int* myDst = sDstA[pi];
        float4 zv[8];
#pragma unroll
        for (int pp = 0; pp < 8; pp++) {
            int e = pp * 16 + eh;
            zv[pp] = __ldg((const float4*)(g_z + (size_t)mySrc[e] * HID) + q);
        }
        if (hn && t < 128) {
            sSrcA[ni][t] = eidx[nt * TILE_E + t];
            sDstA[ni][t] = eidx[N_EDGES + nt * TILE_E + t];
        }

        MBARRIER_WAIT_PARITY(mmb, mph); mph ^= 1;
        TCGEN05_FENCE_AFTER();

        // A is drained by the MMA now: issue next tile's copy into the same
        // buffer so it overlaps LDTM staging + epilogue below.
        if (hn && t == 0) {
            MBARRIER_EXPECT_TX(cmb, EA_TILE_BYTES);
            CP_BULK_G2S(sb_u + OFF_A,
                        (const void*)(g_eA + (size_t)nt * EA_TILE_BYTES),
                        EA_TILE_BYTES, cmb);
        }

        // stage TMEM -> sM with float4 STS (stride-68 rows: aligned + conflict-free)
        {
            uint32_t d[32];
            TCGEN05_LD_32X32B_X32(d, tmem + half * 32);
            TCGEN05_WAIT_LD();
            TCGEN05_FENCE_BEFORE();
            float4* mp = (float4*)(sM + (subp * 32 + lane) * 68 + half * 32);
#pragma unroll
            for (int j = 0; j < 8; j++)
                mp[j] = make_float4(__uint_as_float(d[4 * j + 0]),
                                    __uint_as_float(d[4 * j + 1]),
                                    __uint_as_float(d[4 * j + 2]),
                                    __uint_as_float(d[4 * j + 3]));
        }
        __syncthreads();

        // coalesced epilogue: 16 lanes per edge cover 64 contiguous floats
#pragma unroll
        for (int pp = 0; pp < 8; pp++) {
            int e = pp * 16 + eh;
            int dst = myDst[e];
            float4 mv = *(const float4*)(sM + e * 68 + q * 4);
            float v0 = fmaxf(mv.x + zv[pp].x + sbm[q * 4 + 0], 0.f);
            float v1 = fmaxf(mv.y + zv[pp].y + sbm[q * 4 + 1], 0.f);
            float v2 = fmaxf(mv.z + zv[pp].z + sbm[q * 4 + 2], 0.f);
            float v3 = fmaxf(mv.w + zv[pp].w + sbm[q * 4 + 3], 0.f);
            red_add_v4(g_agg + (size_t)dst * HID + q * 4, v0, v1, v2, v3);
        }
        __syncthreads();   // protect sM/idx before next iteration
        pi ^= 1;
    }

    __syncthreads();
    if (wid == 0) TCGEN05_DEALLOC(tmem, 64);

#else  // ------------------- SIMT fallback path ----------------------------
    float* sE  = (float*)(sb + FOFF_E);
    float* sWm = (float*)(sb + FOFF_WM);
    float* sWe = (float*)(sb + FOFF_SWE);
    float* sbe = (float*)(sb + FOFF_BE);
    float* sbm = (float*)(sb + FOFF_BM);
    int*   sSrc = (int*)(sb + FOFF_SRC);
    int*   sDst = (int*)(sb + FOFF_DST);

    for (int i = t; i < D_EDGE * HID; i += 256) sWe[i] = We[i];
    if (t < 64) { sbe[t] = be[t]; sbm[t] = bm_l[t]; }
    {
        const float4* w4 = (const float4*)Wm_bot;
        float4* s4 = (float4*)sWm;
        for (int i = t; i < 1024; i += 256) s4[i] = w4[i];
    }

    int r = t >> 1, hf = t & 1;
    int tx = t & 15, ty = t >> 4;

    for (int tile = blockIdx.x; tile < N_TILES; tile += gridDim.x) {
        int eb = tile * TILE_E;
        if (t < 128) {
            sSrc[t] = eidx[eb + t];
            sDst[t] = eidx[N_EDGES + eb + t];
        }
        {
            const float4* e4 = (const float4*)(ef + (size_t)(eb + r) * D_EDGE);
            float4 e0 = __ldg(e4), e1 = __ldg(e4 + 1);
            float xf[8] = {e0.x, e0.y, e0.z, e0.w, e1.x, e1.y, e1.z, e1.w};
#pragma unroll
            for (int g = 0; g < 8; g++) {
                int c0 = hf * 32 + g * 4;
                float4 acc = *(const float4*)(sbe + c0);
#pragma unroll
                for (int k = 0; k < 8; k++) {
                    float4 wv = *(const float4*)(sWe + k * HID + c0);
                    acc.x += xf[k] * wv.x; acc.y += xf[k] * wv.y;
                    acc.z += xf[k] * wv.z; acc.w += xf[k] * wv.w;
                }
                acc.x = fmaxf(acc.x, 0.f); acc.y = fmaxf(acc.y, 0.f);
                acc.z = fmaxf(acc.z, 0.f); acc.w = fmaxf(acc.w, 0.f);
                *(float4*)(sE + r * 68 + c0) = acc;
            }
        }
        __syncthreads();

        float acc[8][4] = {};
        const float4* sW4 = (const float4*)sWm;
        const float4* sE4 = (const float4*)sE;
#pragma unroll 4
        for (int kq = 0; kq < 16; kq++) {
            float4 w0 = sW4[(4 * kq + 0) * 16 + tx];
            float4 w1 = sW4[(4 * kq + 1) * 16 + tx];
            float4 w2 = sW4[(4 * kq + 2) * 16 + tx];
            float4 w3 = sW4[(4 * kq + 3) * 16 + tx];
#pragma unroll
            for (int e8 = 0; e8 < 8; e8++) {
                float4 xv = sE4[(ty * 8 + e8) * 17 + kq];
                acc[e8][0] += xv.x * w0.x + xv.y * w1.x + xv.z * w2.x + xv.w * w3.x;
                acc[e8][1] += xv.x * w0.y + xv.y * w1.y + xv.z * w2.y + xv.w * w3.y;
                acc[e8][2] += xv.x * w0.z + xv.y * w1.z + xv.z * w2.z + xv.w * w3.z;
                acc[e8][3] += xv.x * w0.w + xv.y * w1.w + xv.z * w2.w + xv.w * w3.w;
            }
        }
        float b0 = sbm[tx * 4], b1 = sbm[tx * 4 + 1], b2 = sbm[tx * 4 + 2], b3 = sbm[tx * 4 + 3];
#pragma unroll
        for (int e8 = 0; e8 < 8; e8++) {
            int e = ty * 8 + e8;
            int src = sSrc[e], dst = sDst[e];
            float4 zv = __ldg((const float4*)(g_z + (size_t)src * HID) + tx);
            float v0 = fmaxf(acc[e8][0] + zv.x + b0, 0.f);
            float v1 = fmaxf(acc[e8][1] + zv.y + b1, 0.f);
            float v2 = fmaxf(acc[e8][2] + zv.z + b2, 0.f);
            float v3 = fmaxf(acc[e8][3] + zv.w + b3, 0.f);
            red_add_v4(g_agg + (size_t)dst * HID + tx * 4, v0, v1, v2, v3);
        }
        __syncthreads();
    }
#endif
}

// ---------------------------------------------------------------------------
// h = relu(NF @ Wn + bn);  z = h @ Wm_top[layer 0]   (fused)
__global__ void __launch_bounds__(256)
node_proj_kernel(const float* __restrict__ nf,
                 const float* __restrict__ Wn,
                 const float* __restrict__ bn,
                 const float* __restrict__ Wm_top) {
    __shared__ float sWn[D_NODE * HID];
    __shared__ float sbn[HID];
    __shared__ float sWm[HID * HID];
    __shared__ float sX[64 * 68];
    int t = threadIdx.x;
    int nb = blockIdx.x * 64;

    for (int i = t; i < D_NODE * HID; i += 256) sWn[i] = Wn[i];
    if (t < HID) sbn[t] = bn[t];
    {
        const float4* w4 = (const float4*)Wm_top;
        float4* s4 = (float4*)sWm;
        for (int i = t; i < 1024; i += 256) s4[i] = w4[i];
    }
    __syncthreads();

    {
        int r = t >> 2, cg = (t & 3) * 16;
        int node = nb + r;
        float xv[D_NODE];
#pragma unroll
        for (int k = 0; k < D_NODE; k++) xv[k] = 0.f;
        if (node < N_NODES) {
            const float4* xp = (const float4*)(nf + (size_t)node * D_NODE);
            float4 x0 = xp[0], x1 = xp[1], x2 = xp[2], x3 = xp[3];
            xv[0] = x0.x; xv[1] = x0.y; xv[2] = x0.z; xv[3] = x0.w;
            xv[4] = x1.x; xv[5] = x1.y; xv[6] = x1.z; xv[7] = x1.w;
            xv[8] = x2.x; xv[9] = x2.y; xv[10] = x2.z; xv[11] = x2.w;
            xv[12] = x3.x; xv[13] = x3.y; xv[14] = x3.z; xv[15] = x3.w;
        }
        float hv[16];
#pragma unroll
        for (int j = 0; j < 16; j++) {
            int col = cg + j;
            float a = sbn[col];
#pragma unroll
            for (int k = 0; k < D_NODE; k++) a += xv[k] * sWn[k * HID + col];
            hv[j] = fmaxf(a, 0.f);
            sX[r * 68 + col] = hv[j];
        }
        if (node < N_NODES) {
            float4* o = (float4*)(g_h + (size_t)node * HID + cg);
            o[0] = make_float4(hv[0], hv[1], hv[2], hv[3]);
            o[1] = make_float4(hv[4], hv[5], hv[6], hv[7]);
            o[2] = make_float4(hv[8], hv[9], hv[10], hv[11]);
            o[3] = make_float4(hv[12], hv[13], hv[14], hv[15]);
        }
    }
    __syncthreads();

    int tx = t & 15, ty = t >> 4;
    float acc[4][4] = {};
    const float4* sW4 = (const float4*)sWm;
    const float4* sX4 = (const float4*)sX;
#pragma unroll 4
    for (int kq = 0; kq < 16; kq++) {
        float4 w0 = sW4[(4 * kq + 0) * 16 + tx];
        float4 w1 = sW4[(4 * kq + 1) * 16 + tx];
        float4 w2 = sW4[(4 * kq + 2) * 16 + tx];
        float4 w3 = sW4[(4 * kq + 3) * 16 + tx];
#pragma unroll
        for (int ee = 0; ee < 4; ee++) {
            float4 xv = sX4[(ty * 4 + ee) * 17 + kq];
            acc[ee][0] += xv.x * w0.x + xv.y * w1.x + xv.z * w2.x + xv.w * w3.x;
            acc[ee][1] += xv.x * w0.y + xv.y * w1.y + xv.z * w2.y + xv.w * w3.y;
            acc[ee][2] += xv.x * w0.z + xv.y * w1.z + xv.z * w2.z + xv.w * w3.z;
            acc[ee][3] += xv.x * w0.w + xv.y * w1.w + xv.z * w2.w + xv.w * w3.w;
        }
    }
#pragma unroll
    for (int ee = 0; ee < 4; ee++) {
        int node = nb + ty * 4 + ee;
        if (node >= N_NODES) continue;
        *(float4*)(g_z + (size_t)node * HID + tx * 4) =
            make_float4(acc[ee][0], acc[ee][1], acc[ee][2], acc[ee][3]);
    }
}

// ---------------------------------------------------------------------------
__global__ void zero_agg_kernel() {
    int i = blockIdx.x * blockDim.x + threadIdx.x;
    float4* p = (float4*)g_agg;
    const int n4 = N_NODES * HID / 4;
    for (int j = i; j < n4; j += gridDim.x * blockDim.x)
        p[j] = make_float4(0.f, 0.f, 0.f, 0.f);
    if (blockIdx.x == 0 && threadIdx.x < HID) g_gsum[threadIdx.x] = 0.f;
}

// ---------------------------------------------------------------------------
// 128-node tiles, 2 CTAs/SM: h = relu([h, agg] @ Wu_l + bu_l) + h ; zeroes agg;
// optional z = h_new @ Wm_next (layers 0..N-2) OR fused gsum (last layer).
__global__ void __launch_bounds__(256, 2)
node_update_kernel(const float* __restrict__ Wu_l,
                   const float* __restrict__ bu_l,
                   const float* __restrict__ Wm_next,
                   int compute_z) {
    extern __shared__ float sm[];
    float* sW = sm;            // 8192 floats
    float* sX = sm + 8192;     // 128 x 132 = 16896 floats
    float* sb = sm + 25088;    // 64 floats
    int t = threadIdx.x;
    int nb = blockIdx.x * 128;

    {
        const float4* w4 = (const float4*)Wu_l;
        float4* s4 = (float4*)sW;
        for (int i = t; i < 2048; i += 256) s4[i] = w4[i];
        if (t < 64) sb[t] = bu_l[t];
    }
    const float4 z4 = make_float4(0.f, 0.f, 0.f, 0.f);
#pragma unroll
    for (int i = 0; i < 8; i++) {
        int id = t + 256 * i;        // 2048 tasks = 128 rows x 16 quads
        int r = id >> 4, qq = id & 15;
        int node = nb + r;
        float4 vh = z4, va = z4;
        if (node < N_NODES) {
            vh = *(const float4*)(g_h + (size_t)node * HID + qq * 4);
            va = *(const float4*)(g_agg + (size_t)node * HID + qq * 4);
            *(float4*)(g_agg + (size_t)node * HID + qq * 4) = z4;
        }
        *(float4*)(sX + r * 132 + qq * 4) = vh;
        *(float4*)(sX + r * 132 + 64 + qq * 4) = va;
    }
    __syncthreads();

    int tx = t & 15, ty = t >> 4;
    float acc[8][4] = {};
    const float4* sW4 = (const float4*)sW;
    const float4* sX4 = (const float4*)sX;
#pragma unroll 4
    for (int kq = 0; kq < 32; kq++) {
        float4 w0 = sW4[(4 * kq + 0) * 16 + tx];
        float4 w1 = sW4[(4 * kq + 1) * 16 + tx];
        float4 w2 = sW4[(4 * kq + 2) * 16 + tx];
        float4 w3 = sW4[(4 * kq + 3) * 16 + tx];
#pragma unroll
        for (int ee = 0; ee < 8; ee++) {
            float4 xv = sX4[(ty * 8 + ee) * 33 + kq];
            acc[ee][0] += xv.x * w0.x + xv.y * w1.x + xv.z * w2.x + xv.w * w3.x;
            acc[ee][1] += xv.x * w0.y + xv.y * w1.y + xv.z * w2.y + xv.w * w3.y;
            acc[ee][2] += xv.x * w0.z + xv.y * w1.z + xv.z * w2.z + xv.w * w3.z;
            acc[ee][3] += xv.x * w0.w + xv.y * w1.w + xv.z * w2.w + xv.w * w3.w;
        }
    }
    __syncthreads();   // all GEMM reads of sX/sW complete before overwrite

    float csum[4] = {0.f, 0.f, 0.f, 0.f};
#pragma unroll
    for (int ee = 0; ee < 8; ee++) {
        int r = ty * 8 + ee;
        int node = nb + r;
#pragma unroll
        for (int c = 0; c < 4; c++) {
            int col = tx * 4 + c;
            float hold = sX[r * 132 + col];
            float hn = fmaxf(acc[ee][c] + sb[col], 0.f) + hold;
            sX[r * 132 + col] = hn;
            if (node < N_NODES) {
                g_h[(size_t)node * HID + col] = hn;
                if (!compute_z) csum[c] += hn;
            }
        }
    }

    if (compute_z) {
        __syncthreads();
        {
            const float4* w4 = (const float4*)Wm_next;
            float4* s4 = (float4*)sW;
            for (int i = t; i < 1024; i += 256) s4[i] = w4[i];
        }
        __syncthreads();
        float acz[8][4] = {};
#pragma unroll 4
        for (int kq = 0; kq < 16; kq++) {
            float4 w0 = sW4[(4 * kq + 0) * 16 + tx];
            float4 w1 = sW4[(4 * kq + 1) * 16 + tx];
            float4 w2 = sW4[(4 * kq + 2) * 16 + tx];
            float4 w3 = sW4[(4 * kq + 3) * 16 + tx];
#pragma unroll
            for (int ee = 0; ee < 8; ee++) {
                float4 xv = sX4[(ty * 8 + ee) * 33 + kq];
                acz[ee][0] += xv.x * w0.x + xv.y * w1.x + xv.z * w2.x + xv.w * w3.x;
                acz[ee][1] += xv.x * w0.y + xv.y * w1.y + xv.z * w2.y + xv.w * w3.y;
                acz[ee][2] += xv.x * w0.z + xv.y * w1.z + xv.z * w2.z + xv.w * w3.z;
                acz[ee][3] += xv.x * w0.w + xv.y * w1.w + xv.z * w2.w + xv.w * w3.w;
            }
        }
#pragma unroll
        for (int ee = 0; ee < 8; ee++) {
            int node = nb + ty * 8 + ee;
            if (node >= N_NODES) continue;
            *(float4*)(g_z + (size_t)node * HID + tx * 4) =
                make_float4(acz[ee][0], acz[ee][1], acz[ee][2], acz[ee][3]);
        }
    } else {
        // fused gsum: column sums of h_new for the graph embedding
        __syncthreads();
        if (t < 64) sW[t] = 0.f;
        __syncthreads();
#pragma unroll
        for (int c = 0; c < 4; c++) atomicAdd(&sW[tx * 4 + c], csum[c]);
        __syncthreads();
        if (t < 64) atomicAdd(&g_gsum[t], sW[t]);
    }
}

// ---------------------------------------------------------------------------
// scores
__global__ void __launch_bounds__(256)
score_kernel(const int* __restrict__ od,
             const float* __restrict__ Ws1, const float* __restrict__ bs1,
             const float* __restrict__ Ws2, const float* __restrict__ bs2,
             float* __restrict__ out) {
    extern __shared__ float sm[];
    float* sW  = sm;
    float* sX  = sm + 8192;
    float* sb  = sm + 16640;
    float* sw2 = sm + 16704;
    int*   sA  = (int*)(sm + 16768);
    int*   sB  = (int*)(sm + 16832);
    int t = threadIdx.x;
    int pb = blockIdx.x * 64;

    {
        const float4* w4 = (const float4*)Ws1;
        float4* s4 = (float4*)sW;
        for (int i = t; i < 2048; i += 256) s4[i] = w4[i];
        if (t < 64) {
            sb[t] = bs1[t];
            sw2[t] = Ws2[t];
            int p = pb + t;
            sA[t] = (p < N_OD) ? od[p] : 0;
            sB[t] = (p < N_OD) ? od[N_OD + p] : 0;
        }
    }
    __syncthreads();
#pragma unroll
    for (int i = 0; i < 4; i++) {
        int id = t + 256 * i;
        int r = id >> 4, q = id & 15;
        *(float4*)(sX + r * 132 + q * 4) =
            *(const float4*)(g_h + (size_t)sA[r] * HID + q * 4);
        *(float4*)(sX + r * 132 + 64 + q * 4) =
            *(const float4*)(g_h + (size_t)sB[r] * HID + q * 4);
    }
    __syncthreads();

    int tx = t & 15, ty = t >> 4;
    float acc[4][4] = {};
    const float4* sW4 = (const float4*)sW;
    const float4* sX4 = (const float4*)sX;
#pragma unroll 4
    for (int kq = 0; kq < 32; kq++) {
        float4 w0 = sW4[(4 * kq + 0) * 16 + tx];
        float4 w1 = sW4[(4 * kq + 1) * 16 + tx];
        float4 w2 = sW4[(4 * kq + 2) * 16 + tx];
        float4 w3 = sW4[(4 * kq + 3) * 16 + tx];
#pragma unroll
        for (int ee = 0; ee < 4; ee++) {
            float4 xv = sX4[(ty * 4 + ee) * 33 + kq];
            acc[ee][0] += xv.x * w0.x + xv.y * w1.x + xv.z * w2.x + xv.w * w3.x;
            acc[ee][1] += xv.x * w0.y + xv.y * w1.y + xv.z * w2.y + xv.w * w3.y;
            acc[ee][2] += xv.x * w0.z + xv.y * w1.z + xv.z * w2.z + xv.w * w3.z;
            acc[ee][3] += xv.x * w0.w + xv.y * w1.w + xv.z * w2.w + xv.w * w3.w;
        }
    }
    float part[4];
#pragma unroll
    for (int ee = 0; ee < 4; ee++) {
        float s = 0.f;
#pragma unroll
        for (int c = 0; c < 4; c++) {
            int col = tx * 4 + c;
            s += fmaxf(acc[ee][c] + sb[col], 0.f) * sw2[col];
        }
        part[ee] = s;
    }
#pragma unroll
    for (int off = 8; off >= 1; off >>= 1) {
#pragma unroll
        for (int ee = 0; ee < 4; ee++)
            part[ee] += __shfl_xor_sync(0xffffffffu, part[ee], off);
    }
    if (tx == 0) {
        float b2 = bs2[0];
#pragma unroll
        for (int ee = 0; ee < 4; ee++) {
            int p = pb + ty * 4 + ee;
            if (p < N_OD) out[p] = part[ee] + b2;
        }
    }
}

// ---------------------------------------------------------------------------
__global__ void khead_kernel(const float* __restrict__ ts,
                             const float* __restrict__ Wk1, const float* __restrict__ bk1,
                             const float* __restrict__ Wk2, const float* __restrict__ bk2,
                             const float* __restrict__ Wk3, const float* __restrict__ bk3,
                             float* __restrict__ out, int out_size) {
    __shared__ float x[68];
    __shared__ float h1[32];
    __shared__ float h2[16];
    int t = threadIdx.x;
    if (t < 64) x[t] = g_gsum[t] * (1.0f / (float)N_NODES);
    if (t < 4)  x[64 + t] = ts[t];
    __syncthreads();
    if (t < 32) {
        float a = bk1[t];
        for (int i = 0; i < 68; i++) a += x[i] * Wk1[i * 32 + t];
        h1[t] = fmaxf(a, 0.f);
    }
    __syncthreads();
    if (t < 16) {
        float a = bk2[t];
        for (int i = 0; i < 32; i++) a += h1[i] * Wk2[i * 16 + t];
        h2[t] = fmaxf(a, 0.f);
    }
    __syncthreads();
    if (t == 0) {
        float a = bk3[0];
        for (int i = 0; i < 16; i++) a += h2[i] * Wk3[i];
        float sig = 1.f / (1.f + expf(-a));
        out[out_size - 1] = 1.0f + sig * 49.0f;
    }
}

// ---------------------------------------------------------------------------
extern "C" void kernel_launch(void* const* d_in, const int* in_sizes, int n_in,
                              void* d_out, int out_size) {
    const float* nf   = (const float*)d_in[0];
    const int*   eidx = (const int*)d_in[1];
    const float* ef   = (const float*)d_in[2];
    const int*   od   = (const int*)d_in[3];
    const float* ts   = (const float*)d_in[4];
    const float* Wn   = (const float*)d_in[5];
    const float* bn   = (const float*)d_in[6];
    const float* We   = (const float*)d_in[7];
    const float* be   = (const float*)d_in[8];
    const float* Wm   = (const float*)d_in[9];
    const float* bm   = (const float*)d_in[10];
    const float* Wu   = (const float*)d_in[11];
    const float* bu   = (const float*)d_in[12];
    const float* Ws1  = (const float*)d_in[13];
    const float* bs1  = (const float*)d_in[14];
    const float* Ws2  = (const float*)d_in[15];
    const float* bs2  = (const float*)d_in[16];
    const float* Wk1  = (const float*)d_in[17];
    const float* bk1  = (const float*)d_in[18];
    const float* Wk2  = (const float*)d_in[19];
    const float* bk2  = (const float*)d_in[20];
    const float* Wk3  = (const float*)d_in[21];
    const float* bk3  = (const float*)d_in[22];
    float* out = (float*)d_out;

    const int SMEM_UPD   = 100864;
    const int SMEM_SCORE = 67584;
    cudaFuncSetAttribute(edge_msg_kernel, cudaFuncAttributeMaxDynamicSharedMemorySize, SMEM_EDGE_BYTES);
    cudaFuncSetAttribute(node_update_kernel, cudaFuncAttributeMaxDynamicSharedMemorySize, SMEM_UPD);
    cudaFuncSetAttribute(score_kernel, cudaFuncAttributeMaxDynamicSharedMemorySize, SMEM_SCORE);

    // one-time: e tiles in pre-swizzled fp16 layout
    edge_e_kernel<<<N_TILES, 256>>>(ef, We, be);
    // h + z(layer0) fused
    node_proj_kernel<<<(N_NODES + 63) / 64, 256>>>(nf, Wn, bn, Wm);
    zero_agg_kernel<<<3125, 256>>>();

    for (int l = 0; l < N_LAYERS; l++) {
        const float* Wm_l = Wm + (size_t)l * 2 * HID * HID;
        const float* Wm_next = Wm + (size_t)(l + 1 < N_LAYERS ? l + 1 : l) * 2 * HID * HID;
        edge_msg_kernel<<<296, 256, SMEM_EDGE_BYTES>>>(
            eidx, ef, We, be, Wm_l + (size_t)HID * HID, bm + (size_t)l * HID);
        node_update_kernel<<<(N_NODES + 127) / 128, 256, SMEM_UPD>>>(
            Wu + (size_t)l * 2 * HID * HID, bu + (size_t)l * HID,
            Wm_next, l + 1 < N_LAYERS ? 1 : 0);
    }

    khead_kernel<<<1, 64>>>(ts, Wk1, bk1, Wk2, bk2, Wk3, bk3, out, out_size);
    score_kernel<<<(N_OD + 63) / 64, 256, SMEM_SCORE>>>(od, Ws1, bs1, Ws2, bs2, out);
}

// round 15
// speedup vs baseline: 1.1800x; 1.0206x over previous
#include <cuda_runtime.h>
#include <cuda_bf16.h>
#include <cuda_fp16.h>
#include <math.h>
#include <stdint.h>

#define N_NODES 50000
#define N_EDGES 1200000
#define N_OD    10000
#define D_NODE  16
#define D_EDGE  8
#define HID     64
#define N_LAYERS 3
#define TILE_E  128
#define N_TILES (N_EDGES / TILE_E)   // 9375 exactly
#define EA_TILE_BYTES 16384          // fp16 e tile: 128 rows x 128B

#if defined(__CUDA_ARCH__) && (defined(__CUDA_ARCH_FEAT_SM103_ALL) || defined(__CUDA_ARCH_FEAT_SM100_ALL))
#define USE_TC 1
#else
#define USE_TC 0
#endif

// persistent scratch
__device__ float g_h[N_NODES * HID];
__device__ float g_agg[N_NODES * HID];
__device__ __half g_z[N_NODES * HID];    // z = h @ Wm_top (per layer), fp16
__device__ float g_gsum[HID];
// layer-invariant edge features, fp16, pre-swizzled A-tile layout
__device__ __align__(1024) char g_eA[(size_t)N_TILES * EA_TILE_BYTES];

// ---------------------------------------------------------------------------
// helpers
// ---------------------------------------------------------------------------
__device__ __forceinline__ void red_add_v4(float* p, float a, float b, float c, float d) {
    asm volatile("red.global.add.v4.f32 [%0], {%1, %2, %3, %4};"
                 :: "l"(p), "f"(a), "f"(b), "f"(c), "f"(d) : "memory");
}

#if USE_TC
__device__ __forceinline__ uint32_t elect_one_pred() {
    uint32_t pred;
    asm volatile(
        "{\n\t.reg .pred p;\n\t"
        "elect.sync _|p, 0xFFFFFFFF;\n\t"
        "selp.b32 %0, 1, 0, p;\n\t}"
        : "=r"(pred));
    return pred;
}
#endif

__device__ __forceinline__ uint32_t smem_u32(const void* p) {
    uint32_t a;
    asm("{ .reg .u64 t; cvta.to.shared.u64 t, %1; cvt.u32.u64 %0, t; }"
        : "=r"(a) : "l"(p));
    return a;
}
#define SW128(o) ((o) ^ (((o) >> 3) & 0x70))

static constexpr uint64_t SMEM_DESC_BASE_SW128 =
    (uint64_t(2)  << 61) | (uint64_t(1) << 46) | (uint64_t(64) << 32) | (uint64_t(1) << 16);
#define MAKE_SMEM_DESC(base_addr) \
    (SMEM_DESC_BASE_SW128 | ((uint64_t)((base_addr) >> 4) & 0x3FFF))

#if USE_TC
#define TCGEN05_ALLOC(smem_result_addr, nCols) \
    asm volatile("tcgen05.alloc.cta_group::1.sync.aligned.shared::cta.b32 [%0], %1;" \
        :: "r"((uint32_t)(smem_result_addr)), "r"((uint32_t)(nCols)) : "memory")
#define TCGEN05_DEALLOC(tmem_addr, nCols) \
    asm volatile("tcgen05.dealloc.cta_group::1.sync.aligned.b32 %0, %1;" \
        :: "r"(tmem_addr), "r"((uint32_t)(nCols)))
#define TCGEN05_RELINQ() \
    asm volatile("tcgen05.relinquish_alloc_permit.cta_group::1.sync.aligned;")
#define TCGEN05_COMMIT(mbar_smem_addr) \
    asm volatile("tcgen05.commit.cta_group::1.mbarrier::arrive::one.shared::cluster.b64 [%0];" \
        :: "r"((uint32_t)(mbar_smem_addr)) : "memory")
#define TCGEN05_WAIT_LD() \
    asm volatile("tcgen05.wait::ld.sync.aligned;" ::: "memory")
#define TCGEN05_FENCE_BEFORE() \
    asm volatile("tcgen05.fence::before_thread_sync;" ::: "memory")
#define TCGEN05_FENCE_AFTER() \
    asm volatile("tcgen05.fence::after_thread_sync;" ::: "memory")
#define FENCE_PROXY_ASYNC() \
    asm volatile("fence.proxy.async.shared::cta;" ::: "memory")
#define MBARRIER_INIT(mbar, count) \
    asm volatile("mbarrier.init.shared.b64 [%0], %1;" \
        :: "r"((uint32_t)(mbar)), "r"((uint32_t)(count)) : "memory")
#define MBARRIER_EXPECT_TX(mbar, bytes) \
    asm volatile("mbarrier.arrive.expect_tx.shared.b64 _, [%0], %1;" \
        :: "r"((uint32_t)(mbar)), "r"((uint32_t)(bytes)) : "memory")
#define CP_BULK_G2S(dst, src, bytes, mbar) \
    asm volatile("cp.async.bulk.shared::cluster.global.mbarrier::complete_tx::bytes [%0], [%1], %2, [%3];" \
        :: "r"((uint32_t)(dst)), "l"(src), "r"((uint32_t)(bytes)), "r"((uint32_t)(mbar)) : "memory")
#define MBARRIER_WAIT_PARITY(mbar_smem_addr, phase_parity) do { \
    uint32_t _mbar = (uint32_t)(mbar_smem_addr); \
    uint32_t _parity = (uint32_t)(phase_parity); \
    uint32_t _done; \
    asm volatile( \
        "{\n\t.reg .pred p;\n\t" \
        "mbarrier.try_wait.parity.acquire.cta.shared::cta.b64 p, [%1], %2;\n\t" \
        "selp.b32 %0, 1, 0, p;\n\t}" \
        : "=r"(_done) : "r"(_mbar), "r"(_parity) : "memory"); \
    if (!_done) { \
        asm volatile( \
            "{\n\t.reg .pred P1;\n\t" \
            "WAIT_LOOP_%=:\n\t" \
            "mbarrier.try_wait.parity.acquire.cta.shared::cta.b64 P1, [%0], %1, 0x989680;\n\t" \
            "@P1 bra.uni WAIT_DONE_%=;\n\t" \
            "bra.uni WAIT_LOOP_%=;\n\t" \
            "WAIT_DONE_%=:\n\t}" \
            :: "r"(_mbar), "r"(_parity) : "memory"); \
    } \
} while(0)

#define TCGEN05_LD_32X32B_X32(r, tmem_addr) \
    asm volatile( \
        "tcgen05.ld.sync.aligned.32x32b.x32.b32 " \
        "{%0, %1, %2, %3, %4, %5, %6, %7, " \
        " %8, %9, %10, %11, %12, %13, %14, %15, " \
        " %16, %17, %18, %19, %20, %21, %22, %23, " \
        " %24, %25, %26, %27, %28, %29, %30, %31}, [%32];" \
        : "=r"((r)[0]),  "=r"((r)[1]),  "=r"((r)[2]),  "=r"((r)[3]), \
          "=r"((r)[4]),  "=r"((r)[5]),  "=r"((r)[6]),  "=r"((r)[7]), \
          "=r"((r)[8]),  "=r"((r)[9]),  "=r"((r)[10]), "=r"((r)[11]), \
          "=r"((r)[12]), "=r"((r)[13]), "=r"((r)[14]), "=r"((r)[15]), \
          "=r"((r)[16]), "=r"((r)[17]), "=r"((r)[18]), "=r"((r)[19]), \
          "=r"((r)[20]), "=r"((r)[21]), "=r"((r)[22]), "=r"((r)[23]), \
          "=r"((r)[24]), "=r"((r)[25]), "=r"((r)[26]), "=r"((r)[27]), \
          "=r"((r)[28]), "=r"((r)[29]), "=r"((r)[30]), "=r"((r)[31]) \
        : "r"(tmem_addr))

__device__ __forceinline__ void mma_f16_ss(uint32_t d_tmem, uint64_t a_desc,
                                           uint64_t b_desc, uint32_t idesc,
                                           uint32_t acc) {
    asm volatile(
        "{\n\t.reg .pred p;\n\t"
        "setp.ne.u32 p, %5, 0;\n\t"
        "tcgen05.mma.cta_group::1.kind::f16 [%0], %1, %2, %3, {%4, %4, %4, %4}, p;\n\t"
        "}"
        :: "r"(d_tmem), "l"(a_desc), "l"(b_desc), "r"(idesc), "r"(0u), "r"(acc)
        : "memory");
}
#endif // USE_TC

// pack 4 floats to fp16x4 (uint2)
__device__ __forceinline__ uint2 pack_h4(float a, float b, float c, float d) {
    __half2 p0 = __floats2half2_rn(a, b);
    __half2 p1 = __floats2half2_rn(c, d);
    uint2 v;
    v.x = *reinterpret_cast<uint32_t*>(&p0);
    v.y = *reinterpret_cast<uint32_t*>(&p1);
    return v;
}

// idesc: D=F32, A=FP16, B=FP16, N=64, M=128
#define MMA_IDESC 0x08100010u

// tensor-path smem byte offsets (from 1024-aligned base) — single fp16 A buf,
// round-11 late-prefetch structure
#define OFF_A    0        // 16KB
#define OFF_W_HI 16384    // 8KB
#define OFF_W_LO 24576    // 8KB
#define OFF_SM   32768    // 128 x 68 floats = 34816
#define OFF_BM   67584    // 64 floats
#define OFF_SRC0 67840    // 128 ints
#define OFF_SRC1 68352
#define OFF_DST0 68864
#define OFF_DST1 69376
#define OFF_TPTR 69888
#define OFF_CMB  69896
#define OFF_MMB  69904
// fallback-path smem offsets
#define FOFF_E    0       // 128 x 68 floats = 34816B
#define FOFF_WM   34816   // 64 x 64 floats = 16384B
#define FOFF_SWE  51200
#define FOFF_BE   53248
#define FOFF_BM   53504
#define FOFF_SRC  53760
#define FOFF_DST  54272
#define SMEM_EDGE_BYTES 71936

// ---------------------------------------------------------------------------
// One-time: e = relu(EF @ We + be), fp16, pre-swizzled A-tile layout.
// ---------------------------------------------------------------------------
__global__ void __launch_bounds__(256)
edge_e_kernel(const float* __restrict__ ef,
              const float* __restrict__ We,
              const float* __restrict__ be) {
    __shared__ float sWe[D_EDGE * HID];
    __shared__ float sbe[HID];
    int t = threadIdx.x;
    for (int i = t; i < D_EDGE * HID; i += 256) sWe[i] = We[i];
    if (t < 64) sbe[t] = be[t];
    __syncthreads();

    int tile = blockIdx.x;
    int eb = tile * TILE_E;
    int r = t >> 1, hf = t & 1;
    char* a_tile = g_eA + (size_t)tile * EA_TILE_BYTES;

    const float4* e4 = (const float4*)(ef + (size_t)(eb + r) * D_EDGE);
    float4 e0 = __ldg(e4), e1 = __ldg(e4 + 1);
    float xf[8] = {e0.x, e0.y, e0.z, e0.w, e1.x, e1.y, e1.z, e1.w};
#pragma unroll
    for (int g = 0; g < 8; g++) {
        int c0 = hf * 32 + g * 4;
        float4 acc = *(const float4*)(sbe + c0);
#pragma unroll
        for (int k = 0; k < 8; k++) {
            float4 wv = *(const float4*)(sWe + k * HID + c0);
            acc.x += xf[k] * wv.x; acc.y += xf[k] * wv.y;
            acc.z += xf[k] * wv.z; acc.w += xf[k] * wv.w;
        }
        acc.x = fmaxf(acc.x, 0.f); acc.y = fmaxf(acc.y, 0.f);
        acc.z = fmaxf(acc.z, 0.f); acc.w = fmaxf(acc.w, 0.f);
        uint2 v = pack_h4(acc.x, acc.y, acc.z, acc.w);
        uint32_t sw = SW128((uint32_t)(r * 128 + c0 * 2));
        *(uint2*)(a_tile + sw) = v;
    }
}

// ---------------------------------------------------------------------------
// Edge message kernel (persistent, single fp16 A buffer, 2 CTAs/SM, LATE
// prefetch): the next tile's copy is issued right after the MMA drains A
// (post-mmb), overlapping the copy with LDTM + epilogue.
//   c = e @ Wm_bot (tcgen05 fp16); m = relu(z[src] + c + bm); agg[dst] += m
// ---------------------------------------------------------------------------
__global__ void __launch_bounds__(256, 2)
edge_msg_kernel(const int* __restrict__ eidx,
                const float* __restrict__ ef,
                const float* __restrict__ We,
                const float* __restrict__ be,
                const float* __restrict__ Wm_bot,
                const float* __restrict__ bm_l) {
    extern __shared__ char raw[];
    char* sb = (char*)(((uintptr_t)raw + 1023) & ~(uintptr_t)1023);
    int t = threadIdx.x;
    int wid = t >> 5;

#if USE_TC
    const uint32_t sb_u = smem_u32(sb);
    float* sbm = (float*)(sb + OFF_BM);
    float* sM  = (float*)(sb + OFF_SM);
    int* sSrcA[2] = {(int*)(sb + OFF_SRC0), (int*)(sb + OFF_SRC1)};
    int* sDstA[2] = {(int*)(sb + OFF_DST0), (int*)(sb + OFF_DST1)};
    uint32_t tptr = sb_u + OFF_TPTR;
    uint32_t cmb  = sb_u + OFF_CMB;
    uint32_t mmb  = sb_u + OFF_MMB;

    if (t < 64) sbm[t] = bm_l[t];

    // stage Wm_bot^T as fp16 hi/lo, SW128 (B operand: [N=64 rows][K=64])
    {
        int n = t & 63, kg = t >> 6;   // kg in 0..3
        for (int k2 = 0; k2 < 16; k2++) {
            int k = kg * 16 + k2;
            float w = Wm_bot[k * HID + n];
            __half wh = __float2half_rn(w);
            __half wl = __float2half_rn(w - __half2float(wh));
            uint32_t sw = SW128((uint32_t)(n * 128 + k * 2));
            *(unsigned short*)(sb + OFF_W_HI + sw) = *reinterpret_cast<unsigned short*>(&wh);
            *(unsigned short*)(sb + OFF_W_LO + sw) = *reinterpret_cast<unsigned short*>(&wl);
        }
    }

    if (t == 0) { MBARRIER_INIT(cmb, 1); MBARRIER_INIT(mmb, 1); }
    if (wid == 0) TCGEN05_ALLOC(tptr, 64);
    __syncthreads();
    uint32_t tmem;
    asm volatile("ld.shared.b32 %0, [%1];" : "=r"(tmem) : "r"(tptr));
    if (wid == 0) TCGEN05_RELINQ();

    const uint64_t dA    = MAKE_SMEM_DESC(sb_u + OFF_A);
    const uint64_t dW_hi = MAKE_SMEM_DESC(sb_u + OFF_W_HI);
    const uint64_t dW_lo = MAKE_SMEM_DESC(sb_u + OFF_W_LO);

    int eh = t >> 4, q = t & 15;        // 16 lanes per edge
    int lane = t & 31;
    int subp = wid & 3, half = wid >> 2;

    FENCE_PROXY_ASYNC();   // W-tile SIMT writes -> async proxy, once
    __syncthreads();

    uint32_t cph = 0, mph = 0;
    int tile = (int)blockIdx.x;
    const int stride = (int)gridDim.x;
    int pi = 0;

    // prologue: copy tile0 into A, load idx into buf0
    if (tile < N_TILES) {
        if (t == 0) {
            MBARRIER_EXPECT_TX(cmb, EA_TILE_BYTES);
            CP_BULK_G2S(sb_u + OFF_A,
                        (const void*)(g_eA + (size_t)tile * EA_TILE_BYTES),
                        EA_TILE_BYTES, cmb);
        }
        if (t < 128) {
            sSrcA[0][t] = eidx[tile * TILE_E + t];
            sDstA[0][t] = eidx[N_EDGES + tile * TILE_E + t];
        }
    }
    __syncthreads();

    for (; tile < N_TILES; tile += stride) {
        int nt = tile + stride;
        bool hn = nt < N_TILES;
        int ni = 1 - pi;

        // elected thread: wait current copy, issue 8 MMA dispatches, commit
        if (wid == 0) {
            if (elect_one_pred()) {
                MBARRIER_WAIT_PARITY(cmb, cph); cph ^= 1;
#pragma unroll
                for (int ks = 0; ks < 4; ks++) {
                    uint64_t off = (uint64_t)(ks * 2);
                    mma_f16_ss(tmem, dA + off, dW_hi + off, MMA_IDESC, ks > 0 ? 1u : 0u);
                    mma_f16_ss(tmem, dA + off, dW_lo + off, MMA_IDESC, 1u);
                }
                TCGEN05_COMMIT(mmb);
            }
        }

        // prefetch z[src] (fp16: 8B per lane) + next idx (both MMA-independent)
        const int* mySrc = sSrcA[pi];
        const int* myDst = sDstA[pi];
        uint2 zr[8];
#pragma unroll
        for (int pp = 0; pp < 8; pp++) {
            int e = pp * 16 + eh;
            zr[pp] = __ldg((const uint2*)(g_z + (size_t)mySrc[e] * HID) + q);
        }
        if (hn && t < 128) {
            sSrcA[ni][t] = eidx[nt * TILE_E + t];
            sDstA[ni][t] = eidx[N_EDGES + nt * TILE_E + t];
        }

        MBARRIER_WAIT_PARITY(mmb, mph); mph ^= 1;
        TCGEN05_FENCE_AFTER();

        // A is drained by the MMA now: issue next tile's copy into the same
        // buffer so it overlaps LDTM staging + epilogue below.
        if (hn && t == 0) {
            MBARRIER_EXPECT_TX(cmb, EA_TILE_BYTES);
            CP_BULK_G2S(sb_u + OFF_A,
                        (const void*)(g_eA + (size_t)nt * EA_TILE_BYTES),
                        EA_TILE_BYTES, cmb);
        }

        // stage TMEM -> sM with float4 STS (stride-68 rows: aligned + conflict-free)
        {
            uint32_t d[32];
            TCGEN05_LD_32X32B_X32(d, tmem + half * 32);
            TCGEN05_WAIT_LD();
            TCGEN05_FENCE_BEFORE();
            float4* mp = (float4*)(sM + (subp * 32 + lane) * 68 + half * 32);
#pragma unroll
            for (int j = 0; j < 8; j++)
                mp[j] = make_float4(__uint_as_float(d[4 * j + 0]),
                                    __uint_as_float(d[4 * j + 1]),
                                    __uint_as_float(d[4 * j + 2]),
                                    __uint_as_float(d[4 * j + 3]));
        }
        __syncthreads();

        // coalesced epilogue: 16 lanes per edge cover 64 contiguous floats
#pragma unroll
        for (int pp = 0; pp < 8; pp++) {
            int e = pp * 16 + eh;
            int dst = myDst[e];
            float4 mv = *(const float4*)(sM + e * 68 + q * 4);
            __half2 zh0 = *reinterpret_cast<__half2*>(&zr[pp].x);
            __half2 zh1 = *reinterpret_cast<__half2*>(&zr[pp].y);
            float2 zf0 = __half22float2(zh0);
            float2 zf1 = __half22float2(zh1);
            float v0 = fmaxf(mv.x + zf0.x + sbm[q * 4 + 0], 0.f);
            float v1 = fmaxf(mv.y + zf0.y + sbm[q * 4 + 1], 0.f);
            float v2 = fmaxf(mv.z + zf1.x + sbm[q * 4 + 2], 0.f);
            float v3 = fmaxf(mv.w + zf1.y + sbm[q * 4 + 3], 0.f);
            red_add_v4(g_agg + (size_t)dst * HID + q * 4, v0, v1, v2, v3);
        }
        __syncthreads();   // protect sM/idx before next iteration
        pi ^= 1;
    }

    __syncthreads();
    if (wid == 0) TCGEN05_DEALLOC(tmem, 64);

#else  // ------------------- SIMT fallback path ----------------------------
    float* sE  = (float*)(sb + FOFF_E);
    float* sWm = (float*)(sb + FOFF_WM);
    float* sWe = (float*)(sb + FOFF_SWE);
    float* sbe = (float*)(sb + FOFF_BE);
    float* sbm = (float*)(sb + FOFF_BM);
    int*   sSrc = (int*)(sb + FOFF_SRC);
    int*   sDst = (int*)(sb + FOFF_DST);

    for (int i = t; i < D_EDGE * HID; i += 256) sWe[i] = We[i];
    if (t < 64) { sbe[t] = be[t]; sbm[t] = bm_l[t]; }
    {
        const float4* w4 = (const float4*)Wm_bot;
        float4* s4 = (float4*)sWm;
        for (int i = t; i < 1024; i += 256) s4[i] = w4[i];
    }

    int r = t >> 1, hf = t & 1;
    int tx = t & 15, ty = t >> 4;

    for (int tile = blockIdx.x; tile < N_TILES; tile += gridDim.x) {
        int eb = tile * TILE_E;
        if (t < 128) {
            sSrc[t] = eidx[eb + t];
            sDst[t] = eidx[N_EDGES + eb + t];
        }
        {
            const float4* e4 = (const float4*)(ef + (size_t)(eb + r) * D_EDGE);
            float4 e0 = __ldg(e4), e1 = __ldg(e4 + 1);
            float xf[8] = {e0.x, e0.y, e0.z, e0.w, e1.x, e1.y, e1.z, e1.w};
#pragma unroll
            for (int g = 0; g < 8; g++) {
                int c0 = hf * 32 + g * 4;
                float4 acc = *(const float4*)(sbe + c0);
#pragma unroll
                for (int k = 0; k < 8; k++) {
                    float4 wv = *(const float4*)(sWe + k * HID + c0);
                    acc.x += xf[k] * wv.x; acc.y += xf[k] * wv.y;
                    acc.z += xf[k] * wv.z; acc.w += xf[k] * wv.w;
                }
                acc.x = fmaxf(acc.x, 0.f); acc.y = fmaxf(acc.y, 0.f);
                acc.z = fmaxf(acc.z, 0.f); acc.w = fmaxf(acc.w, 0.f);
                *(float4*)(sE + r * 68 + c0) = acc;
            }
        }
        __syncthreads();

        float acc[8][4] = {};
        const float4* sW4 = (const float4*)sWm;
        const float4* sE4 = (const float4*)sE;
#pragma unroll 4
        for (int kq = 0; kq < 16; kq++) {
            float4 w0 = sW4[(4 * kq + 0) * 16 + tx];
            float4 w1 = sW4[(4 * kq + 1) * 16 + tx];
            float4 w2 = sW4[(4 * kq + 2) * 16 + tx];
            float4 w3 = sW4[(4 * kq + 3) * 16 + tx];
#pragma unroll
            for (int e8 = 0; e8 < 8; e8++) {
                float4 xv = sE4[(ty * 8 + e8) * 17 + kq];
                acc[e8][0] += xv.x * w0.x + xv.y * w1.x + xv.z * w2.x + xv.w * w3.x;
                acc[e8][1] += xv.x * w0.y + xv.y * w1.y + xv.z * w2.y + xv.w * w3.y;
                acc[e8][2] += xv.x * w0.z + xv.y * w1.z + xv.z * w2.z + xv.w * w3.z;
                acc[e8][3] += xv.x * w0.w + xv.y * w1.w + xv.z * w2.w + xv.w * w3.w;
            }
        }
        float b0 = sbm[tx * 4], b1 = sbm[tx * 4 + 1], b2 = sbm[tx * 4 + 2], b3 = sbm[tx * 4 + 3];
#pragma unroll
        for (int e8 = 0; e8 < 8; e8++) {
            int e = ty * 8 + e8;
            int src = sSrc[e], dst = sDst[e];
            uint2 zrv = __ldg((const uint2*)(g_z + (size_t)src * HID) + tx);
            __half2 zh0 = *reinterpret_cast<__half2*>(&zrv.x);
            __half2 zh1 = *reinterpret_cast<__half2*>(&zrv.y);
            float2 zf0 = __half22float2(zh0);
            float2 zf1 = __half22float2(zh1);
            float v0 = fmaxf(acc[e8][0] + zf0.x + b0, 0.f);
            float v1 = fmaxf(acc[e8][1] + zf0.y + b1, 0.f);
            float v2 = fmaxf(acc[e8][2] + zf1.x + b2, 0.f);
            float v3 = fmaxf(acc[e8][3] + zf1.y + b3, 0.f);
            red_add_v4(g_agg + (size_t)dst * HID + tx * 4, v0, v1, v2, v3);
        }
        __syncthreads();
    }
#endif
}

// ---------------------------------------------------------------------------
// h = relu(NF @ Wn + bn);  z = h @ Wm_top[layer 0]   (fused; z stored fp16)
__global__ void __launch_bounds__(256)
node_proj_kernel(const float* __restrict__ nf,
                 const float* __restrict__ Wn,
                 const float* __restrict__ bn,
                 const float* __restrict__ Wm_top) {
    __shared__ float sWn[D_NODE * HID];
    __shared__ float sbn[HID];
    __shared__ float sWm[HID * HID];
    __shared__ float sX[64 * 68];
    int t = threadIdx.x;
    int nb = blockIdx.x * 64;

    for (int i = t; i < D_NODE * HID; i += 256) sWn[i] = Wn[i];
    if (t < HID) sbn[t] = bn[t];
    {
        const float4* w4 = (const float4*)Wm_top;
        float4* s4 = (float4*)sWm;
        for (int i = t; i < 1024; i += 256) s4[i] = w4[i];
    }
    __syncthreads();

    {
        int r = t >> 2, cg = (t & 3) * 16;
        int node = nb + r;
        float xv[D_NODE];
#pragma unroll
        for (int k = 0; k < D_NODE; k++) xv[k] = 0.f;
        if (node < N_NODES) {
            const float4* xp = (const float4*)(nf + (size_t)node * D_NODE);
            float4 x0 = xp[0], x1 = xp[1], x2 = xp[2], x3 = xp[3];
            xv[0] = x0.x; xv[1] = x0.y; xv[2] = x0.z; xv[3] = x0.w;
            xv[4] = x1.x; xv[5] = x1.y; xv[6] = x1.z; xv[7] = x1.w;
            xv[8] = x2.x; xv[9] = x2.y; xv[10] = x2.z; xv[11] = x2.w;
            xv[12] = x3.x; xv[13] = x3.y; xv[14] = x3.z; xv[15] = x3.w;
        }
        float hv[16];
#pragma unroll
        for (int j = 0; j < 16; j++) {
            int col = cg + j;
            float a = sbn[col];
#pragma unroll
            for (int k = 0; k < D_NODE; k++) a += xv[k] * sWn[k * HID + col];
            hv[j] = fmaxf(a, 0.f);
            sX[r * 68 + col] = hv[j];
        }
        if (node < N_NODES) {
            float4* o = (float4*)(g_h + (size_t)node * HID + cg);
            o[0] = make_float4(hv[0], hv[1], hv[2], hv[3]);
            o[1] = make_float4(hv[4], hv[5], hv[6], hv[7]);
            o[2] = make_float4(hv[8], hv[9], hv[10], hv[11]);
            o[3] = make_float4(hv[12], hv[13], hv[14], hv[15]);
        }
    }
    __syncthreads();

    int tx = t & 15, ty = t >> 4;
    float acc[4][4] = {};
    const float4* sW4 = (const float4*)sWm;
    const float4* sX4 = (const float4*)sX;
#pragma unroll 4
    for (int kq = 0; kq < 16; kq++) {
        float4 w0 = sW4[(4 * kq + 0) * 16 + tx];
        float4 w1 = sW4[(4 * kq + 1) * 16 + tx];
        float4 w2 = sW4[(4 * kq + 2) * 16 + tx];
        float4 w3 = sW4[(4 * kq + 3) * 16 + tx];
#pragma unroll
        for (int ee = 0; ee < 4; ee++) {
            float4 xv = sX4[(ty * 4 + ee) * 17 + kq];
            acc[ee][0] += xv.x * w0.x + xv.y * w1.x + xv.z * w2.x + xv.w * w3.x;
            acc[ee][1] += xv.x * w0.y + xv.y * w1.y + xv.z * w2.y + xv.w * w3.y;
            acc[ee][2] += xv.x * w0.z + xv.y * w1.z + xv.z * w2.z + xv.w * w3.z;
            acc[ee][3] += xv.x * w0.w + xv.y * w1.w + xv.z * w2.w + xv.w * w3.w;
        }
    }
#pragma unroll
    for (int ee = 0; ee < 4; ee++) {
        int node = nb + ty * 4 + ee;
        if (node >= N_NODES) continue;
        *(uint2*)(g_z + (size_t)node * HID + tx * 4) =
            pack_h4(acc[ee][0], acc[ee][1], acc[ee][2], acc[ee][3]);
    }
}

// ---------------------------------------------------------------------------
__global__ void zero_agg_kernel() {
    int i = blockIdx.x * blockDim.x + threadIdx.x;
    float4* p = (float4*)g_agg;
    const int n4 = N_NODES * HID / 4;
    for (int j = i; j < n4; j += gridDim.x * blockDim.x)
        p[j] = make_float4(0.f, 0.f, 0.f, 0.f);
    if (blockIdx.x == 0 && threadIdx.x < HID) g_gsum[threadIdx.x] = 0.f;
}

// ---------------------------------------------------------------------------
// 128-node tiles, 2 CTAs/SM: h = relu([h, agg] @ Wu_l + bu_l) + h ; zeroes agg;
// optional z = h_new @ Wm_next (fp16 store, layers 0..N-2) OR fused gsum.
__global__ void __launch_bounds__(256, 2)
node_update_kernel(const float* __restrict__ Wu_l,
                   const float* __restrict__ bu_l,
                   const float* __restrict__ Wm_next,
                   int compute_z) {
    extern __shared__ float sm[];
    float* sW = sm;            // 8192 floats
    float* sX = sm + 8192;     // 128 x 132 = 16896 floats
    float* sb = sm + 25088;    // 64 floats
    int t = threadIdx.x;
    int nb = blockIdx.x * 128;

    {
        const float4* w4 = (const float4*)Wu_l;
        float4* s4 = (float4*)sW;
        for (int i = t; i < 2048; i += 256) s4[i] = w4[i];
        if (t < 64) sb[t] = bu_l[t];
    }
    const float4 z4 = make_float4(0.f, 0.f, 0.f, 0.f);
#pragma unroll
    for (int i = 0; i < 8; i++) {
        int id = t + 256 * i;        // 2048 tasks = 128 rows x 16 quads
        int r = id >> 4, qq = id & 15;
        int node = nb + r;
        float4 vh = z4, va = z4;
        if (node < N_NODES) {
            vh = *(const float4*)(g_h + (size_t)node * HID + qq * 4);
            va = *(const float4*)(g_agg + (size_t)node * HID + qq * 4);
            *(float4*)(g_agg + (size_t)node * HID + qq * 4) = z4;
        }
        *(float4*)(sX + r * 132 + qq * 4) = vh;
        *(float4*)(sX + r * 132 + 64 + qq * 4) = va;
    }
    __syncthreads();

    int tx = t & 15, ty = t >> 4;
    float acc[8][4] = {};
    const float4* sW4 = (const float4*)sW;
    const float4* sX4 = (const float4*)sX;
#pragma unroll 4
    for (int kq = 0; kq < 32; kq++) {
        float4 w0 = sW4[(4 * kq + 0) * 16 + tx];
        float4 w1 = sW4[(4 * kq + 1) * 16 + tx];
        float4 w2 = sW4[(4 * kq + 2) * 16 + tx];
        float4 w3 = sW4[(4 * kq + 3) * 16 + tx];
#pragma unroll
        for (int ee = 0; ee < 8; ee++) {
            float4 xv = sX4[(ty * 8 + ee) * 33 + kq];
            acc[ee][0] += xv.x * w0.x + xv.y * w1.x + xv.z * w2.x + xv.w * w3.x;
            acc[ee][1] += xv.x * w0.y + xv.y * w1.y + xv.z * w2.y + xv.w * w3.y;
            acc[ee][2] += xv.x * w0.z + xv.y * w1.z + xv.z * w2.z + xv.w * w3.z;
            acc[ee][3] += xv.x * w0.w + xv.y * w1.w + xv.z * w2.w + xv.w * w3.w;
        }
    }
    __syncthreads();   // all GEMM reads of sX/sW complete before overwrite

    float csum[4] = {0.f, 0.f, 0.f, 0.f};
#pragma unroll
    for (int ee = 0; ee < 8; ee++) {
        int r = ty * 8 + ee;
        int node = nb + r;
#pragma unroll
        for (int c = 0; c < 4; c++) {
            int col = tx * 4 + c;
            float hold = sX[r * 132 + col];
            float hn = fmaxf(acc[ee][c] + sb[col], 0.f) + hold;
            sX[r * 132 + col] = hn;
            if (node < N_NODES) {
                g_h[(size_t)node * HID + col] = hn;
                if (!compute_z) csum[c] += hn;
            }
        }
    }

    if (compute_z) {
        __syncthreads();
        {
            const float4* w4 = (const float4*)Wm_next;
            float4* s4 = (float4*)sW;
            for (int i = t; i < 1024; i += 256) s4[i] = w4[i];
        }
        __syncthreads();
        float acz[8][4] = {};
#pragma unroll 4
        for (int kq = 0; kq < 16; kq++) {
            float4 w0 = sW4[(4 * kq + 0) * 16 + tx];
            float4 w1 = sW4[(4 * kq + 1) * 16 + tx];
            float4 w2 = sW4[(4 * kq + 2) * 16 + tx];
            float4 w3 = sW4[(4 * kq + 3) * 16 + tx];
#pragma unroll
            for (int ee = 0; ee < 8; ee++) {
                float4 xv = sX4[(ty * 8 + ee) * 33 + kq];
                acz[ee][0] += xv.x * w0.x + xv.y * w1.x + xv.z * w2.x + xv.w * w3.x;
                acz[ee][1] += xv.x * w0.y + xv.y * w1.y + xv.z * w2.y + xv.w * w3.y;
                acz[ee][2] += xv.x * w0.z + xv.y * w1.z + xv.z * w2.z + xv.w * w3.z;
                acz[ee][3] += xv.x * w0.w + xv.y * w1.w + xv.z * w2.w + xv.w * w3.w;
            }
        }
#pragma unroll
        for (int ee = 0; ee < 8; ee++) {
            int node = nb + ty * 8 + ee;
            if (node >= N_NODES) continue;
            *(uint2*)(g_z + (size_t)node * HID + tx * 4) =
                pack_h4(acz[ee][0], acz[ee][1], acz[ee][2], acz[ee][3]);
        }
    } else {
        // fused gsum: column sums of h_new for the graph embedding
        __syncthreads();
        if (t < 64) sW[t] = 0.f;
        __syncthreads();
#pragma unroll
        for (int c = 0; c < 4; c++) atomicAdd(&sW[tx * 4 + c], csum[c]);
        __syncthreads();
        if (t < 64) atomicAdd(&g_gsum[t], sW[t]);
    }
}

// ---------------------------------------------------------------------------
// scores
__global__ void __launch_bounds__(256)
score_kernel(const int* __restrict__ od,
             const float* __restrict__ Ws1, const float* __restrict__ bs1,
             const float* __restrict__ Ws2, const float* __restrict__ bs2,
             float* __restrict__ out) {
    extern __shared__ float sm[];
    float* sW  = sm;
    float* sX  = sm + 8192;
    float* sb  = sm + 16640;
    float* sw2 = sm + 16704;
    int*   sA  = (int*)(sm + 16768);
    int*   sB  = (int*)(sm + 16832);
    int t = threadIdx.x;
    int pb = blockIdx.x * 64;

    {
        const float4* w4 = (const float4*)Ws1;
        float4* s4 = (float4*)sW;
        for (int i = t; i < 2048; i += 256) s4[i] = w4[i];
        if (t < 64) {
            sb[t] = bs1[t];
            sw2[t] = Ws2[t];
            int p = pb + t;
            sA[t] = (p < N_OD) ? od[p] : 0;
            sB[t] = (p < N_OD) ? od[N_OD + p] : 0;
        }
    }
    __syncthreads();
#pragma unroll
    for (int i = 0; i < 4; i++) {
        int id = t + 256 * i;
        int r = id >> 4, q = id & 15;
        *(float4*)(sX + r * 132 + q * 4) =
            *(const float4*)(g_h + (size_t)sA[r] * HID + q * 4);
        *(float4*)(sX + r * 132 + 64 + q * 4) =
            *(const float4*)(g_h + (size_t)sB[r] * HID + q * 4);
    }
    __syncthreads();

    int tx = t & 15, ty = t >> 4;
    float acc[4][4] = {};
    const float4* sW4 = (const float4*)sW;
    const float4* sX4 = (const float4*)sX;
#pragma unroll 4
    for (int kq = 0; kq < 32; kq++) {
        float4 w0 = sW4[(4 * kq + 0) * 16 + tx];
        float4 w1 = sW4[(4 * kq + 1) * 16 + tx];
        float4 w2 = sW4[(4 * kq + 2) * 16 + tx];
        float4 w3 = sW4[(4 * kq + 3) * 16 + tx];
#pragma unroll
        for (int ee = 0; ee < 4; ee++) {
            float4 xv = sX4[(ty * 4 + ee) * 33 + kq];
            acc[ee][0] += xv.x * w0.x + xv.y * w1.x + xv.z * w2.x + xv.w * w3.x;
            acc[ee][1] += xv.x * w0.y + xv.y * w1.y + xv.z * w2.y + xv.w * w3.y;
            acc[ee][2] += xv.x * w0.z + xv.y * w1.z + xv.z * w2.z + xv.w * w3.z;
            acc[ee][3] += xv.x * w0.w + xv.y * w1.w + xv.z * w2.w + xv.w * w3.w;
        }
    }
    float part[4];
#pragma unroll
    for (int ee = 0; ee < 4; ee++) {
        float s = 0.f;
#pragma unroll
        for (int c = 0; c < 4; c++) {
            int col = tx * 4 + c;
            s += fmaxf(acc[ee][c] + sb[col], 0.f) * sw2[col];
        }
        part[ee] = s;
    }
#pragma unroll
    for (int off = 8; off >= 1; off >>= 1) {
#pragma unroll
        for (int ee = 0; ee < 4; ee++)
            part[ee] += __shfl_xor_sync(0xffffffffu, part[ee], off);
    }
    if (tx == 0) {
        float b2 = bs2[0];
#pragma unroll
        for (int ee = 0; ee < 4; ee++) {
            int p = pb + ty * 4 + ee;
            if (p < N_OD) out[p] = part[ee] + b2;
        }
    }
}

// ---------------------------------------------------------------------------
__global__ void khead_kernel(const float* __restrict__ ts,
                             const float* __restrict__ Wk1, const float* __restrict__ bk1,
                             const float* __restrict__ Wk2, const float* __restrict__ bk2,
                             const float* __restrict__ Wk3, const float* __restrict__ bk3,
                             float* __restrict__ out, int out_size) {
    __shared__ float x[68];
    __shared__ float h1[32];
    __shared__ float h2[16];
    int t = threadIdx.x;
    if (t < 64) x[t] = g_gsum[t] * (1.0f / (float)N_NODES);
    if (t < 4)  x[64 + t] = ts[t];
    __syncthreads();
    if (t < 32) {
        float a = bk1[t];
        for (int i = 0; i < 68; i++) a += x[i] * Wk1[i * 32 + t];
        h1[t] = fmaxf(a, 0.f);
    }
    __syncthreads();
    if (t < 16) {
        float a = bk2[t];
        for (int i = 0; i < 32; i++) a += h1[i] * Wk2[i * 16 + t];
        h2[t] = fmaxf(a, 0.f);
    }
    __syncthreads();
    if (t == 0) {
        float a = bk3[0];
        for (int i = 0; i < 16; i++) a += h2[i] * Wk3[i];
        float sig = 1.f / (1.f + expf(-a));
        out[out_size - 1] = 1.0f + sig * 49.0f;
    }
}

// ---------------------------------------------------------------------------
extern "C" void kernel_launch(void* const* d_in, const int* in_sizes, int n_in,
                              void* d_out, int out_size) {
    const float* nf   = (const float*)d_in[0];
    const int*   eidx = (const int*)d_in[1];
    const float* ef   = (const float*)d_in[2];
    const int*   od   = (const int*)d_in[3];
    const float* ts   = (const float*)d_in[4];
    const float* Wn   = (const float*)d_in[5];
    const float* bn   = (const float*)d_in[6];
    const float* We   = (const float*)d_in[7];
    const float* be   = (const float*)d_in[8];
    const float* Wm   = (const float*)d_in[9];
    const float* bm   = (const float*)d_in[10];
    const float* Wu   = (const float*)d_in[11];
    const float* bu   = (const float*)d_in[12];
    const float* Ws1  = (const float*)d_in[13];
    const float* bs1  = (const float*)d_in[14];
    const float* Ws2  = (const float*)d_in[15];
    const float* bs2  = (const float*)d_in[16];
    const float* Wk1  = (const float*)d_in[17];
    const float* bk1  = (const float*)d_in[18];
    const float* Wk2  = (const float*)d_in[19];
    const float* bk2  = (const float*)d_in[20];
    const float* Wk3  = (const float*)d_in[21];
    const float* bk3  = (const float*)d_in[22];
    float* out = (float*)d_out;

    const int SMEM_UPD   = 100864;
    const int SMEM_SCORE = 67584;
    cudaFuncSetAttribute(edge_msg_kernel, cudaFuncAttributeMaxDynamicSharedMemorySize, SMEM_EDGE_BYTES);
    cudaFuncSetAttribute(node_update_kernel, cudaFuncAttributeMaxDynamicSharedMemorySize, SMEM_UPD);
    cudaFuncSetAttribute(score_kernel, cudaFuncAttributeMaxDynamicSharedMemorySize, SMEM_SCORE);

    // one-time: e tiles in pre-swizzled fp16 layout
    edge_e_kernel<<<N_TILES, 256>>>(ef, We, be);
    // h + z(layer0) fused
    node_proj_kernel<<<(N_NODES + 63) / 64, 256>>>(nf, Wn, bn, Wm);
    zero_agg_kernel<<<3125, 256>>>();

    for (int l = 0; l < N_LAYERS; l++) {
        const float* Wm_l = Wm + (size_t)l * 2 * HID * HID;
        const float* Wm_next = Wm + (size_t)(l + 1 < N_LAYERS ? l + 1 : l) * 2 * HID * HID;
        edge_msg_kernel<<<296, 256, SMEM_EDGE_BYTES>>>(
            eidx, ef, We, be, Wm_l + (size_t)HID * HID, bm + (size_t)l * HID);
        node_update_kernel<<<(N_NODES + 127) / 128, 256, SMEM_UPD>>>(
            Wu + (size_t)l * 2 * HID * HID, bu + (size_t)l * HID,
            Wm_next, l + 1 < N_LAYERS ? 1 : 0);
    }

    khead_kernel<<<1, 64>>>(ts, Wk1, bk1, Wk2, bk2, Wk3, bk3, out, out_size);
    score_kernel<<<(N_OD + 63) / 64, 256, SMEM_SCORE>>>(od, Ws1, bs1, Ws2, bs2, out);
}